// round 14
// baseline (speedup 1.0000x reference)
#include <cuda_runtime.h>
#include <cuda_fp16.h>
#include <math.h>
#include <stdint.h>

// Problem dims (fixed)
#define SQ   2048
#define SKK  3072
#define TT   4096
#define DM   2048
#define NH   16
#define NKV  8
#define HD   128
#define FF   6144

// ---------------------------------------------------------------------------
// Helpers
// ---------------------------------------------------------------------------
__device__ __forceinline__ uint32_t smem_u32(const void* p) {
    uint32_t a;
    asm("{ .reg .u64 t; cvta.to.shared.u64 t, %1; cvt.u32.u64 %0, t; }" : "=r"(a) : "l"(p));
    return a;
}
__device__ __forceinline__ void cp_async16(uint32_t dst, const void* src) {
    asm volatile("cp.async.cg.shared.global [%0], [%1], 16;" :: "r"(dst), "l"(src));
}
#define CP_COMMIT() asm volatile("cp.async.commit_group;" ::: "memory")
#define CP_WAIT1()  asm volatile("cp.async.wait_group 1;" ::: "memory")
#define CP_WAIT0()  asm volatile("cp.async.wait_group 0;" ::: "memory")

// m16n8k16 fp16 mma with fp32 accumulate
__device__ __forceinline__ void mma_f16(float* d, const uint32_t* a, const uint32_t* b) {
    asm volatile(
        "mma.sync.aligned.m16n8k16.row.col.f32.f16.f16.f32 "
        "{%0,%1,%2,%3}, {%4,%5,%6,%7}, {%8,%9}, {%0,%1,%2,%3};"
        : "+f"(d[0]), "+f"(d[1]), "+f"(d[2]), "+f"(d[3])
        : "r"(a[0]), "r"(a[1]), "r"(a[2]), "r"(a[3]), "r"(b[0]), "r"(b[1]));
}
__device__ __forceinline__ void ldsm_x4(uint32_t* q, uint32_t addr) {
    asm volatile("ldmatrix.sync.aligned.m8n8.x4.shared.b16 {%0,%1,%2,%3}, [%4];"
        : "=r"(q[0]), "=r"(q[1]), "=r"(q[2]), "=r"(q[3]) : "r"(addr));
}
__device__ __forceinline__ void ldsm_x4_trans(uint32_t* q, uint32_t addr) {
    asm volatile("ldmatrix.sync.aligned.m8n8.x4.trans.shared.b16 {%0,%1,%2,%3}, [%4];"
        : "=r"(q[0]), "=r"(q[1]), "=r"(q[2]), "=r"(q[3]) : "r"(addr));
}

// ---------------------------------------------------------------------------
// Scratch
// ---------------------------------------------------------------------------
__device__ __half g_hnorm [SQ  * DM];
__device__ __half g_hknorm[SKK * DM];
__device__ __half g_qh    [SQ  * NH  * HD];
__device__ __half g_kh    [SKK * NKV * HD];
__device__ __half g_vh    [SKK * NKV * HD];
__device__ __half g_ctx   [SQ  * NH  * HD];
__device__ float  g_hidden[SQ  * DM];
__device__ __half g_h2    [SQ  * DM];
__device__ __half g_act   [SQ  * FF];
__device__ float  g_cos   [TT * 64];
__device__ float  g_sin   [TT * 64];
__device__ double g_inv   [64];
__device__ __half g_wqh[2048 * 2048];
__device__ __half g_wkh[2048 * 1024];
__device__ __half g_wvh[2048 * 1024];
__device__ __half g_woh[2048 * 2048];
__device__ __half g_wgh[2048 * 6144];
__device__ __half g_wuh[2048 * 6144];
__device__ __half g_wdh[6144 * 2048];

// ---------------------------------------------------------------------------
// Merged f32 -> f16 convert over all 7 weight tensors (one launch)
// ---------------------------------------------------------------------------
struct CvtArgs {
    const float* src[7];
    __half* dst[7];
    int end[7];
};
__global__ void convert_all_kernel(CvtArgs a) {
    int b = blockIdx.x;
    int j = 0, base = 0;
#pragma unroll
    for (int t = 0; t < 6; t++)
        if (b >= a.end[t]) { j = t + 1; base = a.end[t]; }
    int i = (b - base) * 256 + threadIdx.x;
    float4 v = ((const float4*)a.src[j])[i];
    ((__half2*)a.dst[j])[2 * i]     = __floats2half2_rn(v.x, v.y);
    ((__half2*)a.dst[j])[2 * i + 1] = __floats2half2_rn(v.z, v.w);
}

// ---------------------------------------------------------------------------
// RoPE tables (fp64; pow hoisted)
// ---------------------------------------------------------------------------
__global__ void rope_inv_kernel(double* __restrict__ inv) {
    int d = threadIdx.x;
    inv[d] = pow(1.0e6, -((double)(2 * d)) / 128.0);
}
__global__ void rope_table_kernel(const double* __restrict__ inv,
                                  float* __restrict__ ct, float* __restrict__ st) {
    int p = blockIdx.x;
    int d = threadIdx.x;
    double ang = (double)p * inv[d];
    ct[p * 64 + d] = (float)cos(ang);
    st[p * 64 + d] = (float)sin(ang);
}

// ---------------------------------------------------------------------------
// Row RMSNorm (dim=2048), half output
// ---------------------------------------------------------------------------
__global__ void rmsnorm_kernel(const float* __restrict__ x, const float* __restrict__ w,
                               __half* __restrict__ y, int dim) {
    int row = blockIdx.x;
    const float4* xr = (const float4*)(x + (size_t)row * dim);
    const float4* w4 = (const float4*)w;
    __half2* yr = (__half2*)(y + (size_t)row * dim);
    int n4 = dim >> 2;

    float s = 0.f;
    for (int i = threadIdx.x; i < n4; i += blockDim.x) {
        float4 v = xr[i];
        s += v.x * v.x + v.y * v.y + v.z * v.z + v.w * v.w;
    }
#pragma unroll
    for (int o = 16; o > 0; o >>= 1) s += __shfl_xor_sync(0xffffffffu, s, o);

    __shared__ float red[8];
    __shared__ float s_scale;
    int wid = threadIdx.x >> 5, lane = threadIdx.x & 31;
    if (lane == 0) red[wid] = s;
    __syncthreads();
    if (threadIdx.x == 0) {
        float t = 0.f;
        int nw = blockDim.x >> 5;
        for (int i = 0; i < nw; i++) t += red[i];
        s_scale = rsqrtf(t / (float)dim + 1e-6f);
    }
    __syncthreads();
    float sc = s_scale;
    for (int i = threadIdx.x; i < n4; i += blockDim.x) {
        float4 v = xr[i];
        float4 ww = w4[i];
        yr[2 * i]     = __floats2half2_rn(v.x * sc * ww.x, v.y * sc * ww.y);
        yr[2 * i + 1] = __floats2half2_rn(v.z * sc * ww.z, v.w * sc * ww.w);
    }
}

// ---------------------------------------------------------------------------
// Per-head RMSNorm (D=128) + RoPE, in place on half. 4 pairs/block.
// ---------------------------------------------------------------------------
__global__ void qknorm_rope_kernel(__half* __restrict__ x,
                                   const float* __restrict__ nw,
                                   const int* __restrict__ pos,
                                   const float* __restrict__ ct, const float* __restrict__ st,
                                   int nheads) {
    int g = threadIdx.x >> 7;
    int d = threadIdx.x & 127;
    int idx = blockIdx.x * 4 + g;
    int token = idx / nheads;
    int head  = idx - token * nheads;
    __half* row = x + ((size_t)token * nheads + head) * HD;
    float v = __half2float(row[d]);

    float s = v * v;
#pragma unroll
    for (int o = 16; o > 0; o >>= 1) s += __shfl_xor_sync(0xffffffffu, s, o);
    __shared__ float wsum[4][4];
    __shared__ float xs[4][HD];
    if ((d & 31) == 0) wsum[g][d >> 5] = s;
    __syncthreads();
    float tot = wsum[g][0] + wsum[g][1] + wsum[g][2] + wsum[g][3];
    float sc = rsqrtf(tot * (1.f / 128.f) + 1e-6f);
    float xn = v * sc * nw[d];
    xs[g][d] = xn;
    __syncthreads();

    int p = pos[token];
    int j = d & 63;
    float c  = ct[p * 64 + j];
    float sn = st[p * 64 + j];
    float out;
    if (d < 64) out = xn * c - xs[g][d + 64] * sn;
    else        out = xn * c + xs[g][d - 64] * sn;
    row[d] = __float2half_rn(out);
}

// ---------------------------------------------------------------------------
// Shared GEMM tile geometry (BK=128, 2-stage, validated round 12)
// ---------------------------------------------------------------------------
#define G2_A_WORDS   (256 * 64)
#define G2_B_WORDS   (128 * 64)
#define G2_STAGE     (G2_A_WORDS + G2_B_WORDS)
#define G2_SMEM_BYTES (2 * G2_STAGE * 4)

// Generic GEMM: mode 0: C=acc, 1: C=acc+Res, 3: Ch=half(acc)
__global__ void __launch_bounds__(256, 1) mma_gemm_kernel(
    const __half* __restrict__ A, const __half* __restrict__ BT,
    const float* __restrict__ Res,
    float* __restrict__ C, __half* __restrict__ Ch,
    int M, int N, int K, int mode) {
    extern __shared__ float sm[];
    const int tid = threadIdx.x;
    const int lane = tid & 31;
    const int wid = tid >> 5;
    const int warp_m = wid & 3;
    const int warp_n = wid >> 2;
    const int grp = lane >> 2;
    const int tg = lane & 3;
    const int g1 = (lane >> 3) & 1;
    const int g2 = lane >> 4;
    const int r8 = lane & 7;

    const int col0 = blockIdx.x * 128;
    const int row0 = blockIdx.y * 256;
    const __half* Abase = A + (size_t)row0 * K;
    const __half* Bbase = BT + col0;
    const int KT = K >> 7;

    float acc[4][8][4];
#pragma unroll
    for (int mt = 0; mt < 4; mt++)
#pragma unroll
        for (int nt = 0; nt < 8; nt++)
#pragma unroll
            for (int i = 0; i < 4; i++) acc[mt][nt][i] = 0.f;

    auto load_stage = [&](int stg, int kt) {
        uint32_t sa = smem_u32(sm + stg * G2_STAGE);
        uint32_t sb = sa + G2_A_WORDS * 4;
#pragma unroll
        for (int i = 0; i < 16; i++) {
            int chunk = tid + i * 256;
            int m = chunk >> 4;
            int c = chunk & 15;
            int cs = c ^ (m & 7);
            cp_async16(sa + (uint32_t)(m * 256 + cs * 16),
                       Abase + (size_t)m * K + kt * 128 + c * 8);
        }
#pragma unroll
        for (int i = 0; i < 8; i++) {
            int chunk = tid + i * 256;
            int k = chunk >> 4;
            int c = chunk & 15;
            int cs = c ^ (k & 7);
            cp_async16(sb + (uint32_t)(k * 256 + cs * 16),
                       Bbase + (size_t)(kt * 128 + k) * N + c * 8);
        }
    };

    load_stage(0, 0); CP_COMMIT();
    if (KT > 1) load_stage(1, 1);
    CP_COMMIT();

    for (int kt = 0; kt < KT; kt++) {
        if (kt + 1 < KT) { CP_WAIT1(); } else { CP_WAIT0(); }
        __syncthreads();

        uint32_t sa = smem_u32(sm + (kt & 1) * G2_STAGE);
        uint32_t sb = sa + G2_A_WORDS * 4;

#pragma unroll
        for (int s = 0; s < 8; s++) {
            uint32_t bfr[8][2];
#pragma unroll
            for (int nt16 = 0; nt16 < 4; nt16++) {
                int kl = 16 * s + 8 * g1 + r8;
                int ch = (warp_n * 8 + 2 * nt16 + g2) ^ r8;
                uint32_t b4[4];
                ldsm_x4_trans(b4, sb + (uint32_t)(kl * 256 + ch * 16));
                bfr[2 * nt16][0] = b4[0];
                bfr[2 * nt16][1] = b4[1];
                bfr[2 * nt16 + 1][0] = b4[2];
                bfr[2 * nt16 + 1][1] = b4[3];
            }
#pragma unroll
            for (int mt = 0; mt < 4; mt++) {
                int ml = warp_m * 64 + mt * 16 + 8 * g1 + r8;
                int ch = (2 * s + g2) ^ r8;
                uint32_t af[4];
                ldsm_x4(af, sa + (uint32_t)(ml * 256 + ch * 16));
#pragma unroll
                for (int nt = 0; nt < 8; nt++)
                    mma_f16(acc[mt][nt], af, bfr[nt]);
            }
        }
        __syncthreads();
        if (kt + 2 < KT) { load_stage(kt & 1, kt + 2); CP_COMMIT(); }
    }

#pragma unroll
    for (int mt = 0; mt < 4; mt++) {
        int r = row0 + warp_m * 64 + mt * 16 + grp;
#pragma unroll
        for (int nt = 0; nt < 8; nt++) {
            int c = col0 + warp_n * 64 + nt * 8 + 2 * tg;
            size_t o0 = (size_t)r * N + c;
            size_t o1 = (size_t)(r + 8) * N + c;
            float2 v0 = make_float2(acc[mt][nt][0], acc[mt][nt][1]);
            float2 v1 = make_float2(acc[mt][nt][2], acc[mt][nt][3]);
            if (mode == 3) {
                *(__half2*)(Ch + o0) = __floats2half2_rn(v0.x, v0.y);
                *(__half2*)(Ch + o1) = __floats2half2_rn(v1.x, v1.y);
            } else {
                if (mode == 1) {
                    float2 r0 = *(const float2*)(Res + o0);
                    float2 r1 = *(const float2*)(Res + o1);
                    v0.x += r0.x; v0.y += r0.y;
                    v1.x += r1.x; v1.y += r1.y;
                }
                *(float2*)(C + o0) = v0;
                *(float2*)(C + o1) = v1;
            }
        }
    }
}

// ---------------------------------------------------------------------------
// Merged QKV projection: exact-packed 1D grid of 320 CTAs.
// b in [0,128): Q (16 cols x 8 rows); [128,224): K (8 x 12); [224,320): V.
// ---------------------------------------------------------------------------
__global__ void __launch_bounds__(256, 1) qkv_gemm_kernel(
    const __half* __restrict__ hnorm, const __half* __restrict__ hknorm,
    const __half* __restrict__ wq, const __half* __restrict__ wk,
    const __half* __restrict__ wv,
    __half* __restrict__ qh, __half* __restrict__ kh, __half* __restrict__ vh) {
    extern __shared__ float sm[];
    const int tid = threadIdx.x;
    const int lane = tid & 31;
    const int wid = tid >> 5;
    const int warp_m = wid & 3;
    const int warp_n = wid >> 2;
    const int grp = lane >> 2;
    const int tg = lane & 3;
    const int g1 = (lane >> 3) & 1;
    const int g2 = lane >> 4;
    const int r8 = lane & 7;

    int b = blockIdx.x;
    const __half* A;
    const __half* B;
    __half* Out;
    int N, col0, row0;
    if (b < 128) {
        A = hnorm; B = wq; Out = qh; N = 2048;
        col0 = (b & 15) * 128; row0 = (b >> 4) * 256;
    } else if (b < 224) {
        int t = b - 128;
        A = hknorm; B = wk; Out = kh; N = 1024;
        col0 = (t & 7) * 128; row0 = (t >> 3) * 256;
    } else {
        int t = b - 224;
        A = hknorm; B = wv; Out = vh; N = 1024;
        col0 = (t & 7) * 128; row0 = (t >> 3) * 256;
    }
    const int K = DM;

    const __half* Abase = A + (size_t)row0 * K;
    const __half* Bbase = B + col0;
    const int KT = K >> 7;

    float acc[4][8][4];
#pragma unroll
    for (int mt = 0; mt < 4; mt++)
#pragma unroll
        for (int nt = 0; nt < 8; nt++)
#pragma unroll
            for (int i = 0; i < 4; i++) acc[mt][nt][i] = 0.f;

    auto load_stage = [&](int stg, int kt) {
        uint32_t sa = smem_u32(sm + stg * G2_STAGE);
        uint32_t sb = sa + G2_A_WORDS * 4;
#pragma unroll
        for (int i = 0; i < 16; i++) {
            int chunk = tid + i * 256;
            int m = chunk >> 4;
            int c = chunk & 15;
            int cs = c ^ (m & 7);
            cp_async16(sa + (uint32_t)(m * 256 + cs * 16),
                       Abase + (size_t)m * K + kt * 128 + c * 8);
        }
#pragma unroll
        for (int i = 0; i < 8; i++) {
            int chunk = tid + i * 256;
            int k = chunk >> 4;
            int c = chunk & 15;
            int cs = c ^ (k & 7);
            cp_async16(sb + (uint32_t)(k * 256 + cs * 16),
                       Bbase + (size_t)(kt * 128 + k) * N + c * 8);
        }
    };

    load_stage(0, 0); CP_COMMIT();
    load_stage(1, 1); CP_COMMIT();

    for (int kt = 0; kt < KT; kt++) {
        if (kt + 1 < KT) { CP_WAIT1(); } else { CP_WAIT0(); }
        __syncthreads();

        uint32_t sa = smem_u32(sm + (kt & 1) * G2_STAGE);
        uint32_t sb = sa + G2_A_WORDS * 4;

#pragma unroll
        for (int s = 0; s < 8; s++) {
            uint32_t bfr[8][2];
#pragma unroll
            for (int nt16 = 0; nt16 < 4; nt16++) {
                int kl = 16 * s + 8 * g1 + r8;
                int ch = (warp_n * 8 + 2 * nt16 + g2) ^ r8;
                uint32_t b4[4];
                ldsm_x4_trans(b4, sb + (uint32_t)(kl * 256 + ch * 16));
                bfr[2 * nt16][0] = b4[0];
                bfr[2 * nt16][1] = b4[1];
                bfr[2 * nt16 + 1][0] = b4[2];
                bfr[2 * nt16 + 1][1] = b4[3];
            }
#pragma unroll
            for (int mt = 0; mt < 4; mt++) {
                int ml = warp_m * 64 + mt * 16 + 8 * g1 + r8;
                int ch = (2 * s + g2) ^ r8;
                uint32_t af[4];
                ldsm_x4(af, sa + (uint32_t)(ml * 256 + ch * 16));
#pragma unroll
                for (int nt = 0; nt < 8; nt++)
                    mma_f16(acc[mt][nt], af, bfr[nt]);
            }
        }
        __syncthreads();
        if (kt + 2 < KT) { load_stage(kt & 1, kt + 2); CP_COMMIT(); }
    }

#pragma unroll
    for (int mt = 0; mt < 4; mt++) {
        int r = row0 + warp_m * 64 + mt * 16 + grp;
#pragma unroll
        for (int nt = 0; nt < 8; nt++) {
            int c = col0 + warp_n * 64 + nt * 8 + 2 * tg;
            size_t o0 = (size_t)r * N + c;
            size_t o1 = (size_t)(r + 8) * N + c;
            *(__half2*)(Out + o0) = __floats2half2_rn(acc[mt][nt][0], acc[mt][nt][1]);
            *(__half2*)(Out + o1) = __floats2half2_rn(acc[mt][nt][2], acc[mt][nt][3]);
        }
    }
}

// ---------------------------------------------------------------------------
// Fused gate+up+SiLU dual GEMM (validated round 12).
// ---------------------------------------------------------------------------
#define M3_A_WORDS (128 * 64)
#define M3_B_WORDS (128 * 64)
#define M3_STAGE   (M3_A_WORDS + 2 * M3_B_WORDS)
#define M3_SMEM_BYTES (2 * M3_STAGE * 4)

__global__ void __launch_bounds__(256, 1) dual_gemm_silu_kernel(
    const __half* __restrict__ A, const __half* __restrict__ Bg,
    const __half* __restrict__ Bu, __half* __restrict__ Out,
    int M, int N, int K) {
    extern __shared__ float sm[];
    const int tid = threadIdx.x;
    const int lane = tid & 31;
    const int wid = tid >> 5;
    const int warp_m = wid & 3;
    const int warp_n = wid >> 2;
    const int grp = lane >> 2;
    const int tg = lane & 3;
    const int g1 = (lane >> 3) & 1;
    const int g2 = lane >> 4;
    const int r8 = lane & 7;

    const int row0 = blockIdx.y * 128;
    const int col0 = blockIdx.x * 128;
    const __half* Abase = A + (size_t)row0 * K;
    const __half* Bgb = Bg + col0;
    const __half* Bub = Bu + col0;
    const int KT = K >> 7;

    float acc_g[2][8][4], acc_u[2][8][4];
#pragma unroll
    for (int mt = 0; mt < 2; mt++)
#pragma unroll
        for (int nt = 0; nt < 8; nt++)
#pragma unroll
            for (int i = 0; i < 4; i++) { acc_g[mt][nt][i] = 0.f; acc_u[mt][nt][i] = 0.f; }

    auto load_stage = [&](int stg, int kt) {
        uint32_t sa = smem_u32(sm + stg * M3_STAGE);
        uint32_t sg = sa + M3_A_WORDS * 4;
        uint32_t su = sg + M3_B_WORDS * 4;
#pragma unroll
        for (int i = 0; i < 8; i++) {
            int chunk = tid + i * 256;
            int m = chunk >> 4;
            int c = chunk & 15;
            int cs = c ^ (m & 7);
            cp_async16(sa + (uint32_t)(m * 256 + cs * 16),
                       Abase + (size_t)m * K + kt * 128 + c * 8);
        }
#pragma unroll
        for (int i = 0; i < 8; i++) {
            int chunk = tid + i * 256;
            int k = chunk >> 4;
            int c = chunk & 15;
            int cs = c ^ (k & 7);
            cp_async16(sg + (uint32_t)(k * 256 + cs * 16),
                       Bgb + (size_t)(kt * 128 + k) * N + c * 8);
        }
#pragma unroll
        for (int i = 0; i < 8; i++) {
            int chunk = tid + i * 256;
            int k = chunk >> 4;
            int c = chunk & 15;
            int cs = c ^ (k & 7);
            cp_async16(su + (uint32_t)(k * 256 + cs * 16),
                       Bub + (size_t)(kt * 128 + k) * N + c * 8);
        }
    };

    load_stage(0, 0); CP_COMMIT();
    if (KT > 1) load_stage(1, 1);
    CP_COMMIT();

    for (int kt = 0; kt < KT; kt++) {
        if (kt + 1 < KT) { CP_WAIT1(); } else { CP_WAIT0(); }
        __syncthreads();

        uint32_t sa = smem_u32(sm + (kt & 1) * M3_STAGE);
        uint32_t sg = sa + M3_A_WORDS * 4;
        uint32_t su = sg + M3_B_WORDS * 4;

#pragma unroll
        for (int s = 0; s < 8; s++) {
            uint32_t af[2][4];
#pragma unroll
            for (int mt = 0; mt < 2; mt++) {
                int ml = warp_m * 32 + mt * 16 + 8 * g1 + r8;
                int ch = (2 * s + g2) ^ r8;
                ldsm_x4(af[mt], sa + (uint32_t)(ml * 256 + ch * 16));
            }
            {
                uint32_t bfr[8][2];
#pragma unroll
                for (int nt16 = 0; nt16 < 4; nt16++) {
                    int kl = 16 * s + 8 * g1 + r8;
                    int ch = (warp_n * 8 + 2 * nt16 + g2) ^ r8;
                    uint32_t b4[4];
                    ldsm_x4_trans(b4, sg + (uint32_t)(kl * 256 + ch * 16));
                    bfr[2 * nt16][0] = b4[0]; bfr[2 * nt16][1] = b4[1];
                    bfr[2 * nt16 + 1][0] = b4[2]; bfr[2 * nt16 + 1][1] = b4[3];
                }
#pragma unroll
                for (int mt = 0; mt < 2; mt++)
#pragma unroll
                    for (int nt = 0; nt < 8; nt++)
                        mma_f16(acc_g[mt][nt], af[mt], bfr[nt]);
            }
            {
                uint32_t bfr[8][2];
#pragma unroll
                for (int nt16 = 0; nt16 < 4; nt16++) {
                    int kl = 16 * s + 8 * g1 + r8;
                    int ch = (warp_n * 8 + 2 * nt16 + g2) ^ r8;
                    uint32_t b4[4];
                    ldsm_x4_trans(b4, su + (uint32_t)(kl * 256 + ch * 16));
                    bfr[2 * nt16][0] = b4[0]; bfr[2 * nt16][1] = b4[1];
                    bfr[2 * nt16 + 1][0] = b4[2]; bfr[2 * nt16 + 1][1] = b4[3];
                }
#pragma unroll
                for (int mt = 0; mt < 2; mt++)
#pragma unroll
                    for (int nt = 0; nt < 8; nt++)
                        mma_f16(acc_u[mt][nt], af[mt], bfr[nt]);
            }
        }
        __syncthreads();
        if (kt + 2 < KT) { load_stage(kt & 1, kt + 2); CP_COMMIT(); }
    }

#pragma unroll
    for (int mt = 0; mt < 2; mt++) {
        int r = row0 + warp_m * 32 + mt * 16 + grp;
#pragma unroll
        for (int nt = 0; nt < 8; nt++) {
            int c = col0 + warp_n * 64 + nt * 8 + 2 * tg;
            float gx = acc_g[mt][nt][0], gy = acc_g[mt][nt][1];
            float gz = acc_g[mt][nt][2], gw = acc_g[mt][nt][3];
            *(__half2*)(Out + (size_t)r * N + c) = __floats2half2_rn(
                gx / (1.f + expf(-gx)) * acc_u[mt][nt][0],
                gy / (1.f + expf(-gy)) * acc_u[mt][nt][1]);
            *(__half2*)(Out + (size_t)(r + 8) * N + c) = __floats2half2_rn(
                gz / (1.f + expf(-gz)) * acc_u[mt][nt][2],
                gw / (1.f + expf(-gw)) * acc_u[mt][nt][3]);
        }
    }
}

// ---------------------------------------------------------------------------
// FP16 flash attention, GQA-paired, BQ=128, inline mask gather.
// Grid (SQ/128, NKV) = 128 CTAs.
// ---------------------------------------------------------------------------
#define FL_TILES (SKK / 64)
#define FLH_QS   0
#define FLH_KS   16384
#define FLH_VT   24576
#define FLH_PS   32768
#define FLH_PH   40960
#define FLH_MI   45056
#define FLH_LI   45312
#define FLH_CORR 45568
#define FLH_KCOL 45824
#define FLH_QB   45952
#define FL_BYTES ((45952 + 128) * 4)

__global__ void __launch_bounds__(256, 1) flash_tc_kernel(
    const __half* __restrict__ Q, const __half* __restrict__ Kg,
    const __half* __restrict__ Vg, const float* __restrict__ mask,
    const int* __restrict__ hs_idxs, const int* __restrict__ key_idxs,
    __half* __restrict__ ctx) {
    extern __shared__ float sm[];
    float* Qs = sm + FLH_QS;
    float* Ks = sm + FLH_KS;
    float* Vt = sm + FLH_VT;
    float* Ps = sm + FLH_PS;
    float* Ph = sm + FLH_PH;
    float* mi = sm + FLH_MI;
    float* li = sm + FLH_LI;
    float* corr = sm + FLH_CORR;
    int* kcolS = (int*)(sm + FLH_KCOL);   // [2][64]
    int* qbase = (int*)(sm + FLH_QB);     // [128]

    const int tid = threadIdx.x;
    const int lane = tid & 31;
    const int wrp = tid >> 5;
    const int warp_m = wrp & 3;
    const int warp_n = wrp >> 2;
    const int grp = lane >> 2;
    const int tg = lane & 3;
    const int q0 = blockIdx.x << 7;
    const int hk = blockIdx.y;
    const int h0 = hk << 1;

    const float scale = 0.08838834764831845f;
    const float LOG2E = 1.44269504088896340736f;

#pragma unroll
    for (int i = 0; i < 16; i++) {
        int chunk = tid + i * 256;
        int hh = chunk >> 11;
        int rc = chunk & 2047;
        int row = rc >> 4;
        int jc = rc & 15;
        int c = jc >> 3, j = jc & 7;
        int pj = (j + 2 * (row & 3)) & 7;
        cp_async16(smem_u32(Qs + hh * 8192 + (c * 128 + row) * 32 + pj * 4),
                   Q + (size_t)(q0 + row) * (NH * HD) + (h0 + hh) * HD + jc * 8);
    }
#pragma unroll
    for (int i = 0; i < 4; i++) {
        int chunk = tid + i * 256;
        int row = chunk >> 4;
        int jc = chunk & 15;
        int c = jc >> 3, j = jc & 7;
        int pj = (j + 2 * (row & 3)) & 7;
        cp_async16(smem_u32(Ks + (c * 64 + row) * 32 + pj * 4),
                   Kg + (size_t)row * (NKV * HD) + hk * HD + jc * 8);
    }
    CP_COMMIT();

    mi[tid] = -INFINITY;
    li[tid] = 0.f;
    if (tid < 128) qbase[tid] = hs_idxs[q0 + tid] * TT;
    if (tid < 64) kcolS[tid] = key_idxs[tid];

    float acc_o[2][2][8][4];
#pragma unroll
    for (int hh = 0; hh < 2; hh++)
#pragma unroll
        for (int mt = 0; mt < 2; mt++)
#pragma unroll
            for (int nt = 0; nt < 8; nt++)
#pragma unroll
                for (int i = 0; i < 4; i++) acc_o[hh][mt][nt][i] = 0.f;

    const int jp = tid & 31;
    const int dbase = (tid >> 5) * 16;
    uint4 vra[2], vrb[2];
    {
        const __half* pa = Vg + (size_t)(2 * jp) * (NKV * HD) + hk * HD + dbase;
        const __half* pb = Vg + (size_t)(2 * jp + 1) * (NKV * HD) + hk * HD + dbase;
        vra[0] = *(const uint4*)pa; vra[1] = *(const uint4*)(pa + 8);
        vrb[0] = *(const uint4*)pb; vrb[1] = *(const uint4*)(pb + 8);
    }

    for (int kt = 0; kt < FL_TILES; kt++) {
        const int buf = kt & 1;
        const int k0 = kt << 6;
        const float* KsB = Ks + buf * 4096;
        const float* VtB = Vt + buf * 4096;
        const int* kcolB = kcolS + buf * 64;

        __syncthreads();   // (a)

        {
            float* VtW = Vt + buf * 4096;
            const __half* ha = (const __half*)vra;
            const __half* hb = (const __half*)vrb;
            int j = jp >> 2, kin = jp & 3;
#pragma unroll
            for (int d = 0; d < 16; d++) {
                int row = dbase + d;
                int pj = (j + 2 * (row & 3)) & 7;
                *(__half2*)(VtW + row * 32 + pj * 4 + kin) =
                    __halves2half2(ha[d], hb[d]);
            }
        }
        if (kt + 1 < FL_TILES) {
            int k0n = k0 + 64;
#pragma unroll
            for (int i = 0; i < 4; i++) {
                int chunk = tid + i * 256;
                int row = chunk >> 4;
                int jc = chunk & 15;
                int c = jc >> 3, j = jc & 7;
                int pj = (j + 2 * (row & 3)) & 7;
                cp_async16(smem_u32(Ks + (buf ^ 1) * 4096 + (c * 64 + row) * 32 + pj * 4),
                           Kg + (size_t)(k0n + row) * (NKV * HD) + hk * HD + jc * 8);
            }
            CP_COMMIT();
            if (tid < 64) kcolS[(buf ^ 1) * 64 + tid] = key_idxs[k0n + tid];
            const __half* pa = Vg + (size_t)(k0n + 2 * jp) * (NKV * HD) + hk * HD + dbase;
            const __half* pb = Vg + (size_t)(k0n + 2 * jp + 1) * (NKV * HD) + hk * HD + dbase;
            vra[0] = *(const uint4*)pa; vra[1] = *(const uint4*)(pa + 8);
            vrb[0] = *(const uint4*)pb; vrb[1] = *(const uint4*)(pb + 8);
            CP_WAIT1();
        } else {
            CP_WAIT0();
        }
        __syncthreads();   // (b)

#pragma unroll
        for (int hh = 0; hh < 2; hh++) {
            const float* QsH = Qs + hh * 8192;

            // GEMM1: S = Q @ K^T
            float accs[2][4][4];
#pragma unroll
            for (int mt = 0; mt < 2; mt++)
#pragma unroll
                for (int nt = 0; nt < 4; nt++)
#pragma unroll
                    for (int i = 0; i < 4; i++) accs[mt][nt][i] = 0.f;
#pragma unroll
            for (int c = 0; c < 2; c++)
#pragma unroll
                for (int s = 0; s < 4; s++) {
                    int off = 2 * ((4 * s + tg + 4 * (grp & 3)) & 15);
                    uint32_t bf[4][2];
#pragma unroll
                    for (int nt = 0; nt < 4; nt++) {
                        int rb = warp_n * 32 + nt * 8 + grp;
                        float2 bv = *(const float2*)(KsB + (c * 64 + rb) * 32 + off);
                        bf[nt][0] = __float_as_uint(bv.x);
                        bf[nt][1] = __float_as_uint(bv.y);
                    }
#pragma unroll
                    for (int mt = 0; mt < 2; mt++) {
                        int rm = warp_m * 32 + mt * 16 + grp;
                        const float* ab = QsH + (c * 128 + rm) * 32 + off;
                        float2 pa = *(const float2*)ab;
                        float2 qa = *(const float2*)(ab + 8 * 32);
                        uint32_t af[4] = {__float_as_uint(pa.x), __float_as_uint(qa.x),
                                          __float_as_uint(pa.y), __float_as_uint(qa.y)};
#pragma unroll
                        for (int nt = 0; nt < 4; nt++)
                            mma_f16(accs[mt][nt], af, bf[nt]);
                    }
                }

            // scale + inline-gathered mask -> Ps
#pragma unroll
            for (int mt = 0; mt < 2; mt++) {
                int r0 = warp_m * 32 + mt * 16 + grp, r1 = r0 + 8;
                int qm0 = qbase[r0], qm1 = qbase[r1];
#pragma unroll
                for (int nt = 0; nt < 4; nt++) {
                    int cn = warp_n * 32 + nt * 8 + 2 * tg;
                    int kc0 = kcolB[cn], kc1 = kcolB[cn + 1];
                    float2 m0 = make_float2(__ldg(mask + qm0 + kc0),
                                            __ldg(mask + qm0 + kc1));
                    float2 m1 = make_float2(__ldg(mask + qm1 + kc0),
                                            __ldg(mask + qm1 + kc1));
                    int c = cn >> 5, k32 = cn & 31;
                    int pj = ((k32 >> 2) + 2 * (r0 & 3)) & 7;
                    int kin = k32 & 3;
                    float2 o0 = make_float2(accs[mt][nt][0] * scale + m0.x,
                                            accs[mt][nt][1] * scale + m0.y);
                    float2 o1 = make_float2(accs[mt][nt][2] * scale + m1.x,
                                            accs[mt][nt][3] * scale + m1.y);
                    *(float2*)(Ps + (c * 128 + r0) * 32 + pj * 4 + kin) = o0;
                    *(float2*)(Ps + (c * 128 + r1) * 32 + pj * 4 + kin) = o1;
                }
            }
            __syncthreads();   // (c)

            // softmax: 2 threads/row, 32 keys each. Ps -> Ph
            {
                int row = tid >> 1, c = tid & 1;
                const float* base = Ps + (c * 128 + row) * 32;
                float4 v[8];
#pragma unroll
                for (int jj = 0; jj < 8; jj++) {
                    int pjs = (jj + 2 * (row & 3)) & 7;
                    v[jj] = *(const float4*)(base + pjs * 4);
                }
                float m_old = mi[hh * 128 + row];
                float m = m_old;
#pragma unroll
                for (int jj = 0; jj < 8; jj++)
                    m = fmaxf(m, fmaxf(fmaxf(v[jj].x, v[jj].y), fmaxf(v[jj].z, v[jj].w)));
                m = fmaxf(m, __shfl_xor_sync(0xffffffffu, m, 1));
                float l = 0.f;
#pragma unroll
                for (int jj = 0; jj < 8; jj++) {
                    float px = exp2f((v[jj].x - m) * LOG2E);
                    float py = exp2f((v[jj].y - m) * LOG2E);
                    float pz = exp2f((v[jj].z - m) * LOG2E);
                    float pw = exp2f((v[jj].w - m) * LOG2E);
                    l += (px + py) + (pz + pw);
                    int ck0 = c * 16 + jj * 2;
#pragma unroll
                    for (int p = 0; p < 2; p++) {
                        int ck = ck0 + p;
                        int jh = ck >> 2, kinh = ck & 3;
                        int pjh = (jh + 2 * (row & 3)) & 7;
                        __half2 hv = (p == 0) ? __floats2half2_rn(px, py)
                                              : __floats2half2_rn(pz, pw);
                        *(__half2*)(Ph + row * 32 + pjh * 4 + kinh) = hv;
                    }
                }
                l += __shfl_xor_sync(0xffffffffu, l, 1);
                if (c == 0) {
                    float cr = exp2f((m_old - m) * LOG2E);
                    corr[hh * 128 + row] = cr;
                    li[hh * 128 + row] = li[hh * 128 + row] * cr + l;
                    mi[hh * 128 + row] = m;
                }
            }
            __syncthreads();   // (d)

            // rescale + GEMM2: O += P @ V
            {
#pragma unroll
                for (int mt = 0; mt < 2; mt++) {
                    int rm = warp_m * 32 + mt * 16 + grp;
                    float cr0 = corr[hh * 128 + rm];
                    float cr1 = corr[hh * 128 + rm + 8];
#pragma unroll
                    for (int nt = 0; nt < 8; nt++) {
                        acc_o[hh][mt][nt][0] *= cr0; acc_o[hh][mt][nt][1] *= cr0;
                        acc_o[hh][mt][nt][2] *= cr1; acc_o[hh][mt][nt][3] *= cr1;
                    }
                }
#pragma unroll
                for (int s = 0; s < 4; s++) {
                    int off = 2 * ((4 * s + tg + 4 * (grp & 3)) & 15);
                    uint32_t bf[8][2];
#pragma unroll
                    for (int nt = 0; nt < 8; nt++) {
                        int rb = warp_n * 64 + nt * 8 + grp;
                        float2 bv = *(const float2*)(VtB + rb * 32 + off);
                        bf[nt][0] = __float_as_uint(bv.x);
                        bf[nt][1] = __float_as_uint(bv.y);
                    }
#pragma unroll
                    for (int mt = 0; mt < 2; mt++) {
                        int rm = warp_m * 32 + mt * 16 + grp;
                        float2 pa = *(const float2*)(Ph + rm * 32 + off);
                        float2 qa = *(const float2*)(Ph + (rm + 8) * 32 + off);
                        uint32_t af[4] = {__float_as_uint(pa.x), __float_as_uint(qa.x),
                                          __float_as_uint(pa.y), __float_as_uint(qa.y)};
#pragma unroll
                        for (int nt = 0; nt < 8; nt++)
                            mma_f16(acc_o[hh][mt][nt], af, bf[nt]);
                    }
                }
            }
        }
    }

#pragma unroll
    for (int hh = 0; hh < 2; hh++)
#pragma unroll
        for (int mt = 0; mt < 2; mt++) {
            int lr0 = warp_m * 32 + mt * 16 + grp;
            float inv0 = 1.f / li[hh * 128 + lr0];
            float inv1 = 1.f / li[hh * 128 + lr0 + 8];
            __half* p0 = ctx + (size_t)(q0 + lr0) * (NH * HD) + (h0 + hh) * HD;
            __half* p1 = ctx + (size_t)(q0 + lr0 + 8) * (NH * HD) + (h0 + hh) * HD;
#pragma unroll
            for (int nt = 0; nt < 8; nt++) {
                int col = warp_n * 64 + nt * 8 + 2 * tg;
                *(__half2*)(p0 + col) = __floats2half2_rn(acc_o[hh][mt][nt][0] * inv0,
                                                          acc_o[hh][mt][nt][1] * inv0);
                *(__half2*)(p1 + col) = __floats2half2_rn(acc_o[hh][mt][nt][2] * inv1,
                                                          acc_o[hh][mt][nt][3] * inv1);
            }
        }
}

// ---------------------------------------------------------------------------
// Launch sequence. Profiled launch = #4: merged QKV GEMM.
// ---------------------------------------------------------------------------
extern "C" void kernel_launch(void* const* d_in, const int* in_sizes, int n_in,
                              void* d_out, int out_size) {
    const float* hidden_states = (const float*)d_in[0];
    const float* kv_hidden     = (const float*)d_in[1];
    const float* causal_mask   = (const float*)d_in[2];
    const float* w_q    = (const float*)d_in[3];
    const float* w_k    = (const float*)d_in[4];
    const float* w_v    = (const float*)d_in[5];
    const float* w_o    = (const float*)d_in[6];
    const float* q_nw   = (const float*)d_in[7];
    const float* k_nw   = (const float*)d_in[8];
    const float* ln1    = (const float*)d_in[9];
    const float* ln2    = (const float*)d_in[10];
    const float* w_gate = (const float*)d_in[11];
    const float* w_up   = (const float*)d_in[12];
    const float* w_down = (const float*)d_in[13];
    const int* positions    = (const int*)d_in[14];
    const int* kv_positions = (const int*)d_in[15];
    const int* hs_idxs      = (const int*)d_in[16];
    const int* key_idxs     = (const int*)d_in[17];
    float* out = (float*)d_out;

    __half *hnorm, *hknorm, *qh, *kh, *vh, *ctx, *h2, *act;
    float *hid, *ct, *st;
    double* dinv;
    __half *wqh, *wkh, *wvh, *woh, *wgh, *wuh, *wdh;
    cudaGetSymbolAddress((void**)&hnorm,  g_hnorm);
    cudaGetSymbolAddress((void**)&hknorm, g_hknorm);
    cudaGetSymbolAddress((void**)&qh,     g_qh);
    cudaGetSymbolAddress((void**)&kh,     g_kh);
    cudaGetSymbolAddress((void**)&vh,     g_vh);
    cudaGetSymbolAddress((void**)&ctx,    g_ctx);
    cudaGetSymbolAddress((void**)&hid,    g_hidden);
    cudaGetSymbolAddress((void**)&h2,     g_h2);
    cudaGetSymbolAddress((void**)&act,    g_act);
    cudaGetSymbolAddress((void**)&ct,     g_cos);
    cudaGetSymbolAddress((void**)&st,     g_sin);
    cudaGetSymbolAddress((void**)&dinv,   g_inv);
    cudaGetSymbolAddress((void**)&wqh,    g_wqh);
    cudaGetSymbolAddress((void**)&wkh,    g_wkh);
    cudaGetSymbolAddress((void**)&wvh,    g_wvh);
    cudaGetSymbolAddress((void**)&woh,    g_woh);
    cudaGetSymbolAddress((void**)&wgh,    g_wgh);
    cudaGetSymbolAddress((void**)&wuh,    g_wuh);
    cudaGetSymbolAddress((void**)&wdh,    g_wdh);

    cudaFuncSetAttribute(flash_tc_kernel, cudaFuncAttributeMaxDynamicSharedMemorySize,
                         FL_BYTES);
    cudaFuncSetAttribute(mma_gemm_kernel, cudaFuncAttributeMaxDynamicSharedMemorySize,
                         G2_SMEM_BYTES);
    cudaFuncSetAttribute(qkv_gemm_kernel, cudaFuncAttributeMaxDynamicSharedMemorySize,
                         G2_SMEM_BYTES);
    cudaFuncSetAttribute(dual_gemm_silu_kernel, cudaFuncAttributeMaxDynamicSharedMemorySize,
                         M3_SMEM_BYTES);

    CvtArgs ca;
    ca.src[0] = w_q;    ca.dst[0] = wqh;
    ca.src[1] = w_k;    ca.dst[1] = wkh;
    ca.src[2] = w_v;    ca.dst[2] = wvh;
    ca.src[3] = w_o;    ca.dst[3] = woh;
    ca.src[4] = w_gate; ca.dst[4] = wgh;
    ca.src[5] = w_up;   ca.dst[5] = wuh;
    ca.src[6] = w_down; ca.dst[6] = wdh;
    ca.end[0] = 4096;
    ca.end[1] = 4096 + 2048;
    ca.end[2] = 4096 + 2048 + 2048;
    ca.end[3] = 4096 + 2048 + 2048 + 4096;
    ca.end[4] = 4096 + 2048 + 2048 + 4096 + 12288;
    ca.end[5] = 4096 + 2048 + 2048 + 4096 + 12288 + 12288;
    ca.end[6] = 4096 + 2048 + 2048 + 4096 + 12288 + 12288 + 12288;

    // #1..#3
    convert_all_kernel<<<ca.end[6], 256>>>(ca);
    rmsnorm_kernel<<<SQ, 256>>>(hidden_states, ln1, hnorm, DM);
    rmsnorm_kernel<<<SKK, 256>>>(kv_hidden, ln1, hknorm, DM);
    // #4 <- profiled: merged QKV projection (320 exact-packed CTAs)
    qkv_gemm_kernel<<<320, 256, G2_SMEM_BYTES>>>(
        hnorm, hknorm, wqh, wkh, wvh, qh, kh, vh);

    rope_inv_kernel<<<1, 64>>>(dinv);
    rope_table_kernel<<<TT, 64>>>(dinv, ct, st);

    qknorm_rope_kernel<<<SQ * NH / 4, 512>>>(qh, q_nw, positions, ct, st, NH);
    qknorm_rope_kernel<<<SKK * NKV / 4, 512>>>(kh, k_nw, kv_positions, ct, st, NKV);

    // BQ=128 GQA-paired flash with inline mask gather
    flash_tc_kernel<<<dim3(SQ / 128, NKV), 256, FL_BYTES>>>(
        qh, kh, vh, causal_mask, hs_idxs, key_idxs, ctx);

    mma_gemm_kernel<<<dim3(DM / 128, SQ / 256), 256, G2_SMEM_BYTES>>>(
        ctx, woh, hidden_states, hid, nullptr, SQ, DM, 2048, 1);

    rmsnorm_kernel<<<SQ, 256>>>(hid, ln2, h2, DM);

    dual_gemm_silu_kernel<<<dim3(FF / 128, SQ / 128), 256, M3_SMEM_BYTES>>>(
        h2, wgh, wuh, act, SQ, FF, DM);
    mma_gemm_kernel<<<dim3(DM / 128, SQ / 256), 256, G2_SMEM_BYTES>>>(
        act, wdh, hid, out, nullptr, SQ, DM, FF, 1);
}

// round 15
// speedup vs baseline: 1.1321x; 1.1321x over previous
#include <cuda_runtime.h>
#include <cuda_fp16.h>
#include <math.h>
#include <stdint.h>

// Problem dims (fixed)
#define SQ   2048
#define SKK  3072
#define TT   4096
#define DM   2048
#define NH   16
#define NKV  8
#define HD   128
#define FF   6144

// ---------------------------------------------------------------------------
// Helpers
// ---------------------------------------------------------------------------
__device__ __forceinline__ uint32_t smem_u32(const void* p) {
    uint32_t a;
    asm("{ .reg .u64 t; cvta.to.shared.u64 t, %1; cvt.u32.u64 %0, t; }" : "=r"(a) : "l"(p));
    return a;
}
__device__ __forceinline__ void cp_async16(uint32_t dst, const void* src) {
    asm volatile("cp.async.cg.shared.global [%0], [%1], 16;" :: "r"(dst), "l"(src));
}
#define CP_COMMIT() asm volatile("cp.async.commit_group;" ::: "memory")
#define CP_WAIT1()  asm volatile("cp.async.wait_group 1;" ::: "memory")
#define CP_WAIT0()  asm volatile("cp.async.wait_group 0;" ::: "memory")

// m16n8k16 fp16 mma with fp32 accumulate
__device__ __forceinline__ void mma_f16(float* d, const uint32_t* a, const uint32_t* b) {
    asm volatile(
        "mma.sync.aligned.m16n8k16.row.col.f32.f16.f16.f32 "
        "{%0,%1,%2,%3}, {%4,%5,%6,%7}, {%8,%9}, {%0,%1,%2,%3};"
        : "+f"(d[0]), "+f"(d[1]), "+f"(d[2]), "+f"(d[3])
        : "r"(a[0]), "r"(a[1]), "r"(a[2]), "r"(a[3]), "r"(b[0]), "r"(b[1]));
}
__device__ __forceinline__ void ldsm_x4(uint32_t* q, uint32_t addr) {
    asm volatile("ldmatrix.sync.aligned.m8n8.x4.shared.b16 {%0,%1,%2,%3}, [%4];"
        : "=r"(q[0]), "=r"(q[1]), "=r"(q[2]), "=r"(q[3]) : "r"(addr));
}
__device__ __forceinline__ void ldsm_x4_trans(uint32_t* q, uint32_t addr) {
    asm volatile("ldmatrix.sync.aligned.m8n8.x4.trans.shared.b16 {%0,%1,%2,%3}, [%4];"
        : "=r"(q[0]), "=r"(q[1]), "=r"(q[2]), "=r"(q[3]) : "r"(addr));
}

// ---------------------------------------------------------------------------
// Scratch
// ---------------------------------------------------------------------------
__device__ __half g_hnorm [SQ  * DM];
__device__ __half g_hknorm[SKK * DM];
__device__ __half g_qh    [SQ  * NH  * HD];
__device__ __half g_kh    [SKK * NKV * HD];
__device__ __half g_vh    [SKK * NKV * HD];
__device__ __half g_ctx   [SQ  * NH  * HD];
__device__ float  g_hidden[SQ  * DM];
__device__ __half g_h2    [SQ  * DM];
__device__ __half g_act   [SQ  * FF];
__device__ float  g_cos   [TT * 64];
__device__ float  g_sin   [TT * 64];
__device__ double g_inv   [64];
__device__ float  g_mask  [(size_t)SQ * SKK];
__device__ __half g_wqh[2048 * 2048];
__device__ __half g_wkh[2048 * 1024];
__device__ __half g_wvh[2048 * 1024];
__device__ __half g_woh[2048 * 2048];
__device__ __half g_wgh[2048 * 6144];
__device__ __half g_wuh[2048 * 6144];
__device__ __half g_wdh[6144 * 2048];

// ---------------------------------------------------------------------------
// Merged f32 -> f16 convert over all 7 weight tensors (one launch)
// ---------------------------------------------------------------------------
struct CvtArgs {
    const float* src[7];
    __half* dst[7];
    int end[7];
};
__global__ void convert_all_kernel(CvtArgs a) {
    int b = blockIdx.x;
    int j = 0, base = 0;
#pragma unroll
    for (int t = 0; t < 6; t++)
        if (b >= a.end[t]) { j = t + 1; base = a.end[t]; }
    int i = (b - base) * 256 + threadIdx.x;
    float4 v = ((const float4*)a.src[j])[i];
    ((__half2*)a.dst[j])[2 * i]     = __floats2half2_rn(v.x, v.y);
    ((__half2*)a.dst[j])[2 * i + 1] = __floats2half2_rn(v.z, v.w);
}

// ---------------------------------------------------------------------------
// Gather mask: gm[q][k] = mask[hs_idxs[q]*TT + key_idxs[k]]
// ---------------------------------------------------------------------------
__global__ void gather_mask_kernel(const float* __restrict__ mask,
                                   const int* __restrict__ hs,
                                   const int* __restrict__ ki,
                                   float* __restrict__ gm) {
    int q = blockIdx.y;
    int k = blockIdx.x * 256 + threadIdx.x;
    gm[(size_t)q * SKK + k] = __ldg(mask + (size_t)hs[q] * TT + ki[k]);
}

// ---------------------------------------------------------------------------
// RoPE tables (fp64; pow hoisted)
// ---------------------------------------------------------------------------
__global__ void rope_inv_kernel(double* __restrict__ inv) {
    int d = threadIdx.x;
    inv[d] = pow(1.0e6, -((double)(2 * d)) / 128.0);
}
__global__ void rope_table_kernel(const double* __restrict__ inv,
                                  float* __restrict__ ct, float* __restrict__ st) {
    int p = blockIdx.x;
    int d = threadIdx.x;
    double ang = (double)p * inv[d];
    ct[p * 64 + d] = (float)cos(ang);
    st[p * 64 + d] = (float)sin(ang);
}

// ---------------------------------------------------------------------------
// Row RMSNorm (dim=2048), half output. Merged variant: blocks [0,SQ) process
// x1->y1, blocks [SQ, SQ+SKK) process x2->y2 (same weight w).
// ---------------------------------------------------------------------------
__device__ __forceinline__ void rmsnorm_row(const float* xr_, const float* w,
                                            __half* yr_, int dim) {
    const float4* xr = (const float4*)xr_;
    const float4* w4 = (const float4*)w;
    __half2* yr = (__half2*)yr_;
    int n4 = dim >> 2;

    float s = 0.f;
    for (int i = threadIdx.x; i < n4; i += blockDim.x) {
        float4 v = xr[i];
        s += v.x * v.x + v.y * v.y + v.z * v.z + v.w * v.w;
    }
#pragma unroll
    for (int o = 16; o > 0; o >>= 1) s += __shfl_xor_sync(0xffffffffu, s, o);

    __shared__ float red[8];
    __shared__ float s_scale;
    int wid = threadIdx.x >> 5, lane = threadIdx.x & 31;
    if (lane == 0) red[wid] = s;
    __syncthreads();
    if (threadIdx.x == 0) {
        float t = 0.f;
        int nw = blockDim.x >> 5;
        for (int i = 0; i < nw; i++) t += red[i];
        s_scale = rsqrtf(t / (float)dim + 1e-6f);
    }
    __syncthreads();
    float sc = s_scale;
    for (int i = threadIdx.x; i < n4; i += blockDim.x) {
        float4 v = xr[i];
        float4 ww = w4[i];
        yr[2 * i]     = __floats2half2_rn(v.x * sc * ww.x, v.y * sc * ww.y);
        yr[2 * i + 1] = __floats2half2_rn(v.z * sc * ww.z, v.w * sc * ww.w);
    }
}

__global__ void rmsnorm_kernel(const float* __restrict__ x, const float* __restrict__ w,
                               __half* __restrict__ y, int dim) {
    rmsnorm_row(x + (size_t)blockIdx.x * dim, w, y + (size_t)blockIdx.x * dim, dim);
}

__global__ void rmsnorm2_kernel(const float* __restrict__ x1, __half* __restrict__ y1,
                                const float* __restrict__ x2, __half* __restrict__ y2,
                                const float* __restrict__ w, int dim) {
    int row = blockIdx.x;
    if (row < SQ)
        rmsnorm_row(x1 + (size_t)row * dim, w, y1 + (size_t)row * dim, dim);
    else {
        row -= SQ;
        rmsnorm_row(x2 + (size_t)row * dim, w, y2 + (size_t)row * dim, dim);
    }
}

// ---------------------------------------------------------------------------
// Per-head RMSNorm (D=128) + RoPE, in place on half. 4 pairs/block.
// ---------------------------------------------------------------------------
__global__ void qknorm_rope_kernel(__half* __restrict__ x,
                                   const float* __restrict__ nw,
                                   const int* __restrict__ pos,
                                   const float* __restrict__ ct, const float* __restrict__ st,
                                   int nheads) {
    int g = threadIdx.x >> 7;
    int d = threadIdx.x & 127;
    int idx = blockIdx.x * 4 + g;
    int token = idx / nheads;
    int head  = idx - token * nheads;
    __half* row = x + ((size_t)token * nheads + head) * HD;
    float v = __half2float(row[d]);

    float s = v * v;
#pragma unroll
    for (int o = 16; o > 0; o >>= 1) s += __shfl_xor_sync(0xffffffffu, s, o);
    __shared__ float wsum[4][4];
    __shared__ float xs[4][HD];
    if ((d & 31) == 0) wsum[g][d >> 5] = s;
    __syncthreads();
    float tot = wsum[g][0] + wsum[g][1] + wsum[g][2] + wsum[g][3];
    float sc = rsqrtf(tot * (1.f / 128.f) + 1e-6f);
    float xn = v * sc * nw[d];
    xs[g][d] = xn;
    __syncthreads();

    int p = pos[token];
    int j = d & 63;
    float c  = ct[p * 64 + j];
    float sn = st[p * 64 + j];
    float out;
    if (d < 64) out = xn * c - xs[g][d + 64] * sn;
    else        out = xn * c + xs[g][d - 64] * sn;
    row[d] = __float2half_rn(out);
}

// ---------------------------------------------------------------------------
// Shared GEMM tile geometry (BK=128, 2-stage, validated round 12)
// ---------------------------------------------------------------------------
#define G2_A_WORDS   (256 * 64)
#define G2_B_WORDS   (128 * 64)
#define G2_STAGE     (G2_A_WORDS + G2_B_WORDS)
#define G2_SMEM_BYTES (2 * G2_STAGE * 4)

// Generic GEMM: mode 0: C=acc, 1: C=acc+Res, 3: Ch=half(acc)
__global__ void __launch_bounds__(256, 1) mma_gemm_kernel(
    const __half* __restrict__ A, const __half* __restrict__ BT,
    const float* __restrict__ Res,
    float* __restrict__ C, __half* __restrict__ Ch,
    int M, int N, int K, int mode) {
    extern __shared__ float sm[];
    const int tid = threadIdx.x;
    const int lane = tid & 31;
    const int wid = tid >> 5;
    const int warp_m = wid & 3;
    const int warp_n = wid >> 2;
    const int grp = lane >> 2;
    const int tg = lane & 3;
    const int g1 = (lane >> 3) & 1;
    const int g2 = lane >> 4;
    const int r8 = lane & 7;

    const int col0 = blockIdx.x * 128;
    const int row0 = blockIdx.y * 256;
    const __half* Abase = A + (size_t)row0 * K;
    const __half* Bbase = BT + col0;
    const int KT = K >> 7;

    float acc[4][8][4];
#pragma unroll
    for (int mt = 0; mt < 4; mt++)
#pragma unroll
        for (int nt = 0; nt < 8; nt++)
#pragma unroll
            for (int i = 0; i < 4; i++) acc[mt][nt][i] = 0.f;

    auto load_stage = [&](int stg, int kt) {
        uint32_t sa = smem_u32(sm + stg * G2_STAGE);
        uint32_t sb = sa + G2_A_WORDS * 4;
#pragma unroll
        for (int i = 0; i < 16; i++) {
            int chunk = tid + i * 256;
            int m = chunk >> 4;
            int c = chunk & 15;
            int cs = c ^ (m & 7);
            cp_async16(sa + (uint32_t)(m * 256 + cs * 16),
                       Abase + (size_t)m * K + kt * 128 + c * 8);
        }
#pragma unroll
        for (int i = 0; i < 8; i++) {
            int chunk = tid + i * 256;
            int k = chunk >> 4;
            int c = chunk & 15;
            int cs = c ^ (k & 7);
            cp_async16(sb + (uint32_t)(k * 256 + cs * 16),
                       Bbase + (size_t)(kt * 128 + k) * N + c * 8);
        }
    };

    load_stage(0, 0); CP_COMMIT();
    if (KT > 1) load_stage(1, 1);
    CP_COMMIT();

    for (int kt = 0; kt < KT; kt++) {
        if (kt + 1 < KT) { CP_WAIT1(); } else { CP_WAIT0(); }
        __syncthreads();

        uint32_t sa = smem_u32(sm + (kt & 1) * G2_STAGE);
        uint32_t sb = sa + G2_A_WORDS * 4;

#pragma unroll
        for (int s = 0; s < 8; s++) {
            uint32_t bfr[8][2];
#pragma unroll
            for (int nt16 = 0; nt16 < 4; nt16++) {
                int kl = 16 * s + 8 * g1 + r8;
                int ch = (warp_n * 8 + 2 * nt16 + g2) ^ r8;
                uint32_t b4[4];
                ldsm_x4_trans(b4, sb + (uint32_t)(kl * 256 + ch * 16));
                bfr[2 * nt16][0] = b4[0];
                bfr[2 * nt16][1] = b4[1];
                bfr[2 * nt16 + 1][0] = b4[2];
                bfr[2 * nt16 + 1][1] = b4[3];
            }
#pragma unroll
            for (int mt = 0; mt < 4; mt++) {
                int ml = warp_m * 64 + mt * 16 + 8 * g1 + r8;
                int ch = (2 * s + g2) ^ r8;
                uint32_t af[4];
                ldsm_x4(af, sa + (uint32_t)(ml * 256 + ch * 16));
#pragma unroll
                for (int nt = 0; nt < 8; nt++)
                    mma_f16(acc[mt][nt], af, bfr[nt]);
            }
        }
        __syncthreads();
        if (kt + 2 < KT) { load_stage(kt & 1, kt + 2); CP_COMMIT(); }
    }

#pragma unroll
    for (int mt = 0; mt < 4; mt++) {
        int r = row0 + warp_m * 64 + mt * 16 + grp;
#pragma unroll
        for (int nt = 0; nt < 8; nt++) {
            int c = col0 + warp_n * 64 + nt * 8 + 2 * tg;
            size_t o0 = (size_t)r * N + c;
            size_t o1 = (size_t)(r + 8) * N + c;
            float2 v0 = make_float2(acc[mt][nt][0], acc[mt][nt][1]);
            float2 v1 = make_float2(acc[mt][nt][2], acc[mt][nt][3]);
            if (mode == 3) {
                *(__half2*)(Ch + o0) = __floats2half2_rn(v0.x, v0.y);
                *(__half2*)(Ch + o1) = __floats2half2_rn(v1.x, v1.y);
            } else {
                if (mode == 1) {
                    float2 r0 = *(const float2*)(Res + o0);
                    float2 r1 = *(const float2*)(Res + o1);
                    v0.x += r0.x; v0.y += r0.y;
                    v1.x += r1.x; v1.y += r1.y;
                }
                *(float2*)(C + o0) = v0;
                *(float2*)(C + o1) = v1;
            }
        }
    }
}

// ---------------------------------------------------------------------------
// Merged QKV projection: exact-packed 1D grid of 320 CTAs.
// b in [0,128): Q (16 cols x 8 rows); [128,224): K (8 x 12); [224,320): V.
// ---------------------------------------------------------------------------
__global__ void __launch_bounds__(256, 1) qkv_gemm_kernel(
    const __half* __restrict__ hnorm, const __half* __restrict__ hknorm,
    const __half* __restrict__ wq, const __half* __restrict__ wk,
    const __half* __restrict__ wv,
    __half* __restrict__ qh, __half* __restrict__ kh, __half* __restrict__ vh) {
    extern __shared__ float sm[];
    const int tid = threadIdx.x;
    const int lane = tid & 31;
    const int wid = tid >> 5;
    const int warp_m = wid & 3;
    const int warp_n = wid >> 2;
    const int grp = lane >> 2;
    const int tg = lane & 3;
    const int g1 = (lane >> 3) & 1;
    const int g2 = lane >> 4;
    const int r8 = lane & 7;

    int b = blockIdx.x;
    const __half* A;
    const __half* B;
    __half* Out;
    int N, col0, row0;
    if (b < 128) {
        A = hnorm; B = wq; Out = qh; N = 2048;
        col0 = (b & 15) * 128; row0 = (b >> 4) * 256;
    } else if (b < 224) {
        int t = b - 128;
        A = hknorm; B = wk; Out = kh; N = 1024;
        col0 = (t & 7) * 128; row0 = (t >> 3) * 256;
    } else {
        int t = b - 224;
        A = hknorm; B = wv; Out = vh; N = 1024;
        col0 = (t & 7) * 128; row0 = (t >> 3) * 256;
    }
    const int K = DM;

    const __half* Abase = A + (size_t)row0 * K;
    const __half* Bbase = B + col0;
    const int KT = K >> 7;

    float acc[4][8][4];
#pragma unroll
    for (int mt = 0; mt < 4; mt++)
#pragma unroll
        for (int nt = 0; nt < 8; nt++)
#pragma unroll
            for (int i = 0; i < 4; i++) acc[mt][nt][i] = 0.f;

    auto load_stage = [&](int stg, int kt) {
        uint32_t sa = smem_u32(sm + stg * G2_STAGE);
        uint32_t sb = sa + G2_A_WORDS * 4;
#pragma unroll
        for (int i = 0; i < 16; i++) {
            int chunk = tid + i * 256;
            int m = chunk >> 4;
            int c = chunk & 15;
            int cs = c ^ (m & 7);
            cp_async16(sa + (uint32_t)(m * 256 + cs * 16),
                       Abase + (size_t)m * K + kt * 128 + c * 8);
        }
#pragma unroll
        for (int i = 0; i < 8; i++) {
            int chunk = tid + i * 256;
            int k = chunk >> 4;
            int c = chunk & 15;
            int cs = c ^ (k & 7);
            cp_async16(sb + (uint32_t)(k * 256 + cs * 16),
                       Bbase + (size_t)(kt * 128 + k) * N + c * 8);
        }
    };

    load_stage(0, 0); CP_COMMIT();
    load_stage(1, 1); CP_COMMIT();

    for (int kt = 0; kt < KT; kt++) {
        if (kt + 1 < KT) { CP_WAIT1(); } else { CP_WAIT0(); }
        __syncthreads();

        uint32_t sa = smem_u32(sm + (kt & 1) * G2_STAGE);
        uint32_t sb = sa + G2_A_WORDS * 4;

#pragma unroll
        for (int s = 0; s < 8; s++) {
            uint32_t bfr[8][2];
#pragma unroll
            for (int nt16 = 0; nt16 < 4; nt16++) {
                int kl = 16 * s + 8 * g1 + r8;
                int ch = (warp_n * 8 + 2 * nt16 + g2) ^ r8;
                uint32_t b4[4];
                ldsm_x4_trans(b4, sb + (uint32_t)(kl * 256 + ch * 16));
                bfr[2 * nt16][0] = b4[0];
                bfr[2 * nt16][1] = b4[1];
                bfr[2 * nt16 + 1][0] = b4[2];
                bfr[2 * nt16 + 1][1] = b4[3];
            }
#pragma unroll
            for (int mt = 0; mt < 4; mt++) {
                int ml = warp_m * 64 + mt * 16 + 8 * g1 + r8;
                int ch = (2 * s + g2) ^ r8;
                uint32_t af[4];
                ldsm_x4(af, sa + (uint32_t)(ml * 256 + ch * 16));
#pragma unroll
                for (int nt = 0; nt < 8; nt++)
                    mma_f16(acc[mt][nt], af, bfr[nt]);
            }
        }
        __syncthreads();
        if (kt + 2 < KT) { load_stage(kt & 1, kt + 2); CP_COMMIT(); }
    }

#pragma unroll
    for (int mt = 0; mt < 4; mt++) {
        int r = row0 + warp_m * 64 + mt * 16 + grp;
#pragma unroll
        for (int nt = 0; nt < 8; nt++) {
            int c = col0 + warp_n * 64 + nt * 8 + 2 * tg;
            size_t o0 = (size_t)r * N + c;
            size_t o1 = (size_t)(r + 8) * N + c;
            *(__half2*)(Out + o0) = __floats2half2_rn(acc[mt][nt][0], acc[mt][nt][1]);
            *(__half2*)(Out + o1) = __floats2half2_rn(acc[mt][nt][2], acc[mt][nt][3]);
        }
    }
}

// ---------------------------------------------------------------------------
// Fused gate+up+SiLU dual GEMM (validated round 12).
// ---------------------------------------------------------------------------
#define M3_A_WORDS (128 * 64)
#define M3_B_WORDS (128 * 64)
#define M3_STAGE   (M3_A_WORDS + 2 * M3_B_WORDS)
#define M3_SMEM_BYTES (2 * M3_STAGE * 4)

__global__ void __launch_bounds__(256, 1) dual_gemm_silu_kernel(
    const __half* __restrict__ A, const __half* __restrict__ Bg,
    const __half* __restrict__ Bu, __half* __restrict__ Out,
    int M, int N, int K) {
    extern __shared__ float sm[];
    const int tid = threadIdx.x;
    const int lane = tid & 31;
    const int wid = tid >> 5;
    const int warp_m = wid & 3;
    const int warp_n = wid >> 2;
    const int grp = lane >> 2;
    const int tg = lane & 3;
    const int g1 = (lane >> 3) & 1;
    const int g2 = lane >> 4;
    const int r8 = lane & 7;

    const int row0 = blockIdx.y * 128;
    const int col0 = blockIdx.x * 128;
    const __half* Abase = A + (size_t)row0 * K;
    const __half* Bgb = Bg + col0;
    const __half* Bub = Bu + col0;
    const int KT = K >> 7;

    float acc_g[2][8][4], acc_u[2][8][4];
#pragma unroll
    for (int mt = 0; mt < 2; mt++)
#pragma unroll
        for (int nt = 0; nt < 8; nt++)
#pragma unroll
            for (int i = 0; i < 4; i++) { acc_g[mt][nt][i] = 0.f; acc_u[mt][nt][i] = 0.f; }

    auto load_stage = [&](int stg, int kt) {
        uint32_t sa = smem_u32(sm + stg * M3_STAGE);
        uint32_t sg = sa + M3_A_WORDS * 4;
        uint32_t su = sg + M3_B_WORDS * 4;
#pragma unroll
        for (int i = 0; i < 8; i++) {
            int chunk = tid + i * 256;
            int m = chunk >> 4;
            int c = chunk & 15;
            int cs = c ^ (m & 7);
            cp_async16(sa + (uint32_t)(m * 256 + cs * 16),
                       Abase + (size_t)m * K + kt * 128 + c * 8);
        }
#pragma unroll
        for (int i = 0; i < 8; i++) {
            int chunk = tid + i * 256;
            int k = chunk >> 4;
            int c = chunk & 15;
            int cs = c ^ (k & 7);
            cp_async16(sg + (uint32_t)(k * 256 + cs * 16),
                       Bgb + (size_t)(kt * 128 + k) * N + c * 8);
        }
#pragma unroll
        for (int i = 0; i < 8; i++) {
            int chunk = tid + i * 256;
            int k = chunk >> 4;
            int c = chunk & 15;
            int cs = c ^ (k & 7);
            cp_async16(su + (uint32_t)(k * 256 + cs * 16),
                       Bub + (size_t)(kt * 128 + k) * N + c * 8);
        }
    };

    load_stage(0, 0); CP_COMMIT();
    if (KT > 1) load_stage(1, 1);
    CP_COMMIT();

    for (int kt = 0; kt < KT; kt++) {
        if (kt + 1 < KT) { CP_WAIT1(); } else { CP_WAIT0(); }
        __syncthreads();

        uint32_t sa = smem_u32(sm + (kt & 1) * M3_STAGE);
        uint32_t sg = sa + M3_A_WORDS * 4;
        uint32_t su = sg + M3_B_WORDS * 4;

#pragma unroll
        for (int s = 0; s < 8; s++) {
            uint32_t af[2][4];
#pragma unroll
            for (int mt = 0; mt < 2; mt++) {
                int ml = warp_m * 32 + mt * 16 + 8 * g1 + r8;
                int ch = (2 * s + g2) ^ r8;
                ldsm_x4(af[mt], sa + (uint32_t)(ml * 256 + ch * 16));
            }
            {
                uint32_t bfr[8][2];
#pragma unroll
                for (int nt16 = 0; nt16 < 4; nt16++) {
                    int kl = 16 * s + 8 * g1 + r8;
                    int ch = (warp_n * 8 + 2 * nt16 + g2) ^ r8;
                    uint32_t b4[4];
                    ldsm_x4_trans(b4, sg + (uint32_t)(kl * 256 + ch * 16));
                    bfr[2 * nt16][0] = b4[0]; bfr[2 * nt16][1] = b4[1];
                    bfr[2 * nt16 + 1][0] = b4[2]; bfr[2 * nt16 + 1][1] = b4[3];
                }
#pragma unroll
                for (int mt = 0; mt < 2; mt++)
#pragma unroll
                    for (int nt = 0; nt < 8; nt++)
                        mma_f16(acc_g[mt][nt], af[mt], bfr[nt]);
            }
            {
                uint32_t bfr[8][2];
#pragma unroll
                for (int nt16 = 0; nt16 < 4; nt16++) {
                    int kl = 16 * s + 8 * g1 + r8;
                    int ch = (warp_n * 8 + 2 * nt16 + g2) ^ r8;
                    uint32_t b4[4];
                    ldsm_x4_trans(b4, su + (uint32_t)(kl * 256 + ch * 16));
                    bfr[2 * nt16][0] = b4[0]; bfr[2 * nt16][1] = b4[1];
                    bfr[2 * nt16 + 1][0] = b4[2]; bfr[2 * nt16 + 1][1] = b4[3];
                }
#pragma unroll
                for (int mt = 0; mt < 2; mt++)
#pragma unroll
                    for (int nt = 0; nt < 8; nt++)
                        mma_f16(acc_u[mt][nt], af[mt], bfr[nt]);
            }
        }
        __syncthreads();
        if (kt + 2 < KT) { load_stage(kt & 1, kt + 2); CP_COMMIT(); }
    }

#pragma unroll
    for (int mt = 0; mt < 2; mt++) {
        int r = row0 + warp_m * 32 + mt * 16 + grp;
#pragma unroll
        for (int nt = 0; nt < 8; nt++) {
            int c = col0 + warp_n * 64 + nt * 8 + 2 * tg;
            float gx = acc_g[mt][nt][0], gy = acc_g[mt][nt][1];
            float gz = acc_g[mt][nt][2], gw = acc_g[mt][nt][3];
            *(__half2*)(Out + (size_t)r * N + c) = __floats2half2_rn(
                gx / (1.f + expf(-gx)) * acc_u[mt][nt][0],
                gy / (1.f + expf(-gy)) * acc_u[mt][nt][1]);
            *(__half2*)(Out + (size_t)(r + 8) * N + c) = __floats2half2_rn(
                gz / (1.f + expf(-gz)) * acc_u[mt][nt][2],
                gw / (1.f + expf(-gw)) * acc_u[mt][nt][3]);
        }
    }
}

// ---------------------------------------------------------------------------
// FP16 flash attention, GQA-paired, BQ=128, materialized mask (gm).
// Grid (SQ/128, NKV) = 128 CTAs. (Round-13 validated version.)
// ---------------------------------------------------------------------------
#define FL_TILES (SKK / 64)
#define FLH_QS   0
#define FLH_KS   16384
#define FLH_VT   24576
#define FLH_PS   32768
#define FLH_PH   40960
#define FLH_MI   45056
#define FLH_LI   45312
#define FLH_CORR 45568
#define FL_BYTES ((45568 + 256) * 4)

__global__ void __launch_bounds__(256, 1) flash_tc_kernel(
    const __half* __restrict__ Q, const __half* __restrict__ Kg,
    const __half* __restrict__ Vg, const float* __restrict__ gm,
    __half* __restrict__ ctx) {
    extern __shared__ float sm[];
    float* Qs = sm + FLH_QS;
    float* Ks = sm + FLH_KS;
    float* Vt = sm + FLH_VT;
    float* Ps = sm + FLH_PS;
    float* Ph = sm + FLH_PH;
    float* mi = sm + FLH_MI;
    float* li = sm + FLH_LI;
    float* corr = sm + FLH_CORR;

    const int tid = threadIdx.x;
    const int lane = tid & 31;
    const int wrp = tid >> 5;
    const int warp_m = wrp & 3;
    const int warp_n = wrp >> 2;
    const int grp = lane >> 2;
    const int tg = lane & 3;
    const int q0 = blockIdx.x << 7;
    const int hk = blockIdx.y;
    const int h0 = hk << 1;

    const float scale = 0.08838834764831845f;
    const float LOG2E = 1.44269504088896340736f;

#pragma unroll
    for (int i = 0; i < 16; i++) {
        int chunk = tid + i * 256;
        int hh = chunk >> 11;
        int rc = chunk & 2047;
        int row = rc >> 4;
        int jc = rc & 15;
        int c = jc >> 3, j = jc & 7;
        int pj = (j + 2 * (row & 3)) & 7;
        cp_async16(smem_u32(Qs + hh * 8192 + (c * 128 + row) * 32 + pj * 4),
                   Q + (size_t)(q0 + row) * (NH * HD) + (h0 + hh) * HD + jc * 8);
    }
#pragma unroll
    for (int i = 0; i < 4; i++) {
        int chunk = tid + i * 256;
        int row = chunk >> 4;
        int jc = chunk & 15;
        int c = jc >> 3, j = jc & 7;
        int pj = (j + 2 * (row & 3)) & 7;
        cp_async16(smem_u32(Ks + (c * 64 + row) * 32 + pj * 4),
                   Kg + (size_t)row * (NKV * HD) + hk * HD + jc * 8);
    }
    CP_COMMIT();

    mi[tid] = -INFINITY;
    li[tid] = 0.f;

    float acc_o[2][2][8][4];
#pragma unroll
    for (int hh = 0; hh < 2; hh++)
#pragma unroll
        for (int mt = 0; mt < 2; mt++)
#pragma unroll
            for (int nt = 0; nt < 8; nt++)
#pragma unroll
                for (int i = 0; i < 4; i++) acc_o[hh][mt][nt][i] = 0.f;

    const int jp = tid & 31;
    const int dbase = (tid >> 5) * 16;
    uint4 vra[2], vrb[2];
    {
        const __half* pa = Vg + (size_t)(2 * jp) * (NKV * HD) + hk * HD + dbase;
        const __half* pb = Vg + (size_t)(2 * jp + 1) * (NKV * HD) + hk * HD + dbase;
        vra[0] = *(const uint4*)pa; vra[1] = *(const uint4*)(pa + 8);
        vrb[0] = *(const uint4*)pb; vrb[1] = *(const uint4*)(pb + 8);
    }

    for (int kt = 0; kt < FL_TILES; kt++) {
        const int buf = kt & 1;
        const int k0 = kt << 6;
        const float* KsB = Ks + buf * 4096;
        const float* VtB = Vt + buf * 4096;

        __syncthreads();   // (a)

        {
            float* VtW = Vt + buf * 4096;
            const __half* ha = (const __half*)vra;
            const __half* hb = (const __half*)vrb;
            int j = jp >> 2, kin = jp & 3;
#pragma unroll
            for (int d = 0; d < 16; d++) {
                int row = dbase + d;
                int pj = (j + 2 * (row & 3)) & 7;
                *(__half2*)(VtW + row * 32 + pj * 4 + kin) =
                    __halves2half2(ha[d], hb[d]);
            }
        }
        if (kt + 1 < FL_TILES) {
            int k0n = k0 + 64;
#pragma unroll
            for (int i = 0; i < 4; i++) {
                int chunk = tid + i * 256;
                int row = chunk >> 4;
                int jc = chunk & 15;
                int c = jc >> 3, j = jc & 7;
                int pj = (j + 2 * (row & 3)) & 7;
                cp_async16(smem_u32(Ks + (buf ^ 1) * 4096 + (c * 64 + row) * 32 + pj * 4),
                           Kg + (size_t)(k0n + row) * (NKV * HD) + hk * HD + jc * 8);
            }
            CP_COMMIT();
            const __half* pa = Vg + (size_t)(k0n + 2 * jp) * (NKV * HD) + hk * HD + dbase;
            const __half* pb = Vg + (size_t)(k0n + 2 * jp + 1) * (NKV * HD) + hk * HD + dbase;
            vra[0] = *(const uint4*)pa; vra[1] = *(const uint4*)(pa + 8);
            vrb[0] = *(const uint4*)pb; vrb[1] = *(const uint4*)(pb + 8);
            CP_WAIT1();
        } else {
            CP_WAIT0();
        }
        __syncthreads();   // (b)

#pragma unroll
        for (int hh = 0; hh < 2; hh++) {
            const float* QsH = Qs + hh * 8192;

            // GEMM1: S = Q @ K^T (warp tile 32 rows x 32 keys)
            float accs[2][4][4];
#pragma unroll
            for (int mt = 0; mt < 2; mt++)
#pragma unroll
                for (int nt = 0; nt < 4; nt++)
#pragma unroll
                    for (int i = 0; i < 4; i++) accs[mt][nt][i] = 0.f;
#pragma unroll
            for (int c = 0; c < 2; c++)
#pragma unroll
                for (int s = 0; s < 4; s++) {
                    int off = 2 * ((4 * s + tg + 4 * (grp & 3)) & 15);
                    uint32_t bf[4][2];
#pragma unroll
                    for (int nt = 0; nt < 4; nt++) {
                        int rb = warp_n * 32 + nt * 8 + grp;
                        float2 bv = *(const float2*)(KsB + (c * 64 + rb) * 32 + off);
                        bf[nt][0] = __float_as_uint(bv.x);
                        bf[nt][1] = __float_as_uint(bv.y);
                    }
#pragma unroll
                    for (int mt = 0; mt < 2; mt++) {
                        int rm = warp_m * 32 + mt * 16 + grp;
                        const float* ab = QsH + (c * 128 + rm) * 32 + off;
                        float2 pa = *(const float2*)ab;
                        float2 qa = *(const float2*)(ab + 8 * 32);
                        uint32_t af[4] = {__float_as_uint(pa.x), __float_as_uint(qa.x),
                                          __float_as_uint(pa.y), __float_as_uint(qa.y)};
#pragma unroll
                        for (int nt = 0; nt < 4; nt++)
                            mma_f16(accs[mt][nt], af, bf[nt]);
                    }
                }

            // scale + mask -> Ps
#pragma unroll
            for (int mt = 0; mt < 2; mt++) {
                int r0 = warp_m * 32 + mt * 16 + grp, r1 = r0 + 8;
                const float* g0 = gm + (size_t)(q0 + r0) * SKK + k0;
                const float* g1 = gm + (size_t)(q0 + r1) * SKK + k0;
#pragma unroll
                for (int nt = 0; nt < 4; nt++) {
                    int cn = warp_n * 32 + nt * 8 + 2 * tg;
                    float2 m0 = *(const float2*)(g0 + cn);
                    float2 m1 = *(const float2*)(g1 + cn);
                    int c = cn >> 5, k32 = cn & 31;
                    int pj = ((k32 >> 2) + 2 * (r0 & 3)) & 7;
                    int kin = k32 & 3;
                    float2 o0 = make_float2(accs[mt][nt][0] * scale + m0.x,
                                            accs[mt][nt][1] * scale + m0.y);
                    float2 o1 = make_float2(accs[mt][nt][2] * scale + m1.x,
                                            accs[mt][nt][3] * scale + m1.y);
                    *(float2*)(Ps + (c * 128 + r0) * 32 + pj * 4 + kin) = o0;
                    *(float2*)(Ps + (c * 128 + r1) * 32 + pj * 4 + kin) = o1;
                }
            }
            __syncthreads();   // (c)

            // softmax: 2 threads/row, 32 keys each. Ps -> Ph
            {
                int row = tid >> 1, c = tid & 1;
                const float* base = Ps + (c * 128 + row) * 32;
                float4 v[8];
#pragma unroll
                for (int jj = 0; jj < 8; jj++) {
                    int pjs = (jj + 2 * (row & 3)) & 7;
                    v[jj] = *(const float4*)(base + pjs * 4);
                }
                float m_old = mi[hh * 128 + row];
                float m = m_old;
#pragma unroll
                for (int jj = 0; jj < 8; jj++)
                    m = fmaxf(m, fmaxf(fmaxf(v[jj].x, v[jj].y), fmaxf(v[jj].z, v[jj].w)));
                m = fmaxf(m, __shfl_xor_sync(0xffffffffu, m, 1));
                float l = 0.f;
#pragma unroll
                for (int jj = 0; jj < 8; jj++) {
                    float px = exp2f((v[jj].x - m) * LOG2E);
                    float py = exp2f((v[jj].y - m) * LOG2E);
                    float pz = exp2f((v[jj].z - m) * LOG2E);
                    float pw = exp2f((v[jj].w - m) * LOG2E);
                    l += (px + py) + (pz + pw);
                    int ck0 = c * 16 + jj * 2;
#pragma unroll
                    for (int p = 0; p < 2; p++) {
                        int ck = ck0 + p;
                        int jh = ck >> 2, kinh = ck & 3;
                        int pjh = (jh + 2 * (row & 3)) & 7;
                        __half2 hv = (p == 0) ? __floats2half2_rn(px, py)
                                              : __floats2half2_rn(pz, pw);
                        *(__half2*)(Ph + row * 32 + pjh * 4 + kinh) = hv;
                    }
                }
                l += __shfl_xor_sync(0xffffffffu, l, 1);
                if (c == 0) {
                    float cr = exp2f((m_old - m) * LOG2E);
                    corr[hh * 128 + row] = cr;
                    li[hh * 128 + row] = li[hh * 128 + row] * cr + l;
                    mi[hh * 128 + row] = m;
                }
            }
            __syncthreads();   // (d)

            // rescale + GEMM2: O += P @ V
            {
#pragma unroll
                for (int mt = 0; mt < 2; mt++) {
                    int rm = warp_m * 32 + mt * 16 + grp;
                    float cr0 = corr[hh * 128 + rm];
                    float cr1 = corr[hh * 128 + rm + 8];
#pragma unroll
                    for (int nt = 0; nt < 8; nt++) {
                        acc_o[hh][mt][nt][0] *= cr0; acc_o[hh][mt][nt][1] *= cr0;
                        acc_o[hh][mt][nt][2] *= cr1; acc_o[hh][mt][nt][3] *= cr1;
                    }
                }
#pragma unroll
                for (int s = 0; s < 4; s++) {
                    int off = 2 * ((4 * s + tg + 4 * (grp & 3)) & 15);
                    uint32_t bf[8][2];
#pragma unroll
                    for (int nt = 0; nt < 8; nt++) {
                        int rb = warp_n * 64 + nt * 8 + grp;
                        float2 bv = *(const float2*)(VtB + rb * 32 + off);
                        bf[nt][0] = __float_as_uint(bv.x);
                        bf[nt][1] = __float_as_uint(bv.y);
                    }
#pragma unroll
                    for (int mt = 0; mt < 2; mt++) {
                        int rm = warp_m * 32 + mt * 16 + grp;
                        float2 pa = *(const float2*)(Ph + rm * 32 + off);
                        float2 qa = *(const float2*)(Ph + (rm + 8) * 32 + off);
                        uint32_t af[4] = {__float_as_uint(pa.x), __float_as_uint(qa.x),
                                          __float_as_uint(pa.y), __float_as_uint(qa.y)};
#pragma unroll
                        for (int nt = 0; nt < 8; nt++)
                            mma_f16(acc_o[hh][mt][nt], af, bf[nt]);
                    }
                }
            }
        }
    }

#pragma unroll
    for (int hh = 0; hh < 2; hh++)
#pragma unroll
        for (int mt = 0; mt < 2; mt++) {
            int lr0 = warp_m * 32 + mt * 16 + grp;
            float inv0 = 1.f / li[hh * 128 + lr0];
            float inv1 = 1.f / li[hh * 128 + lr0 + 8];
            __half* p0 = ctx + (size_t)(q0 + lr0) * (NH * HD) + (h0 + hh) * HD;
            __half* p1 = ctx + (size_t)(q0 + lr0 + 8) * (NH * HD) + (h0 + hh) * HD;
#pragma unroll
            for (int nt = 0; nt < 8; nt++) {
                int col = warp_n * 64 + nt * 8 + 2 * tg;
                *(__half2*)(p0 + col) = __floats2half2_rn(acc_o[hh][mt][nt][0] * inv0,
                                                          acc_o[hh][mt][nt][1] * inv0);
                *(__half2*)(p1 + col) = __floats2half2_rn(acc_o[hh][mt][nt][2] * inv1,
                                                          acc_o[hh][mt][nt][3] * inv1);
            }
        }
}

// ---------------------------------------------------------------------------
// Launch sequence. Profiled launch = #4: merged QKV GEMM.
// ---------------------------------------------------------------------------
extern "C" void kernel_launch(void* const* d_in, const int* in_sizes, int n_in,
                              void* d_out, int out_size) {
    const float* hidden_states = (const float*)d_in[0];
    const float* kv_hidden     = (const float*)d_in[1];
    const float* causal_mask   = (const float*)d_in[2];
    const float* w_q    = (const float*)d_in[3];
    const float* w_k    = (const float*)d_in[4];
    const float* w_v    = (const float*)d_in[5];
    const float* w_o    = (const float*)d_in[6];
    const float* q_nw   = (const float*)d_in[7];
    const float* k_nw   = (const float*)d_in[8];
    const float* ln1    = (const float*)d_in[9];
    const float* ln2    = (const float*)d_in[10];
    const float* w_gate = (const float*)d_in[11];
    const float* w_up   = (const float*)d_in[12];
    const float* w_down = (const float*)d_in[13];
    const int* positions    = (const int*)d_in[14];
    const int* kv_positions = (const int*)d_in[15];
    const int* hs_idxs      = (const int*)d_in[16];
    const int* key_idxs     = (const int*)d_in[17];
    float* out = (float*)d_out;

    __half *hnorm, *hknorm, *qh, *kh, *vh, *ctx, *h2, *act;
    float *hid, *ct, *st, *gm;
    double* dinv;
    __half *wqh, *wkh, *wvh, *woh, *wgh, *wuh, *wdh;
    cudaGetSymbolAddress((void**)&hnorm,  g_hnorm);
    cudaGetSymbolAddress((void**)&hknorm, g_hknorm);
    cudaGetSymbolAddress((void**)&qh,     g_qh);
    cudaGetSymbolAddress((void**)&kh,     g_kh);
    cudaGetSymbolAddress((void**)&vh,     g_vh);
    cudaGetSymbolAddress((void**)&ctx,    g_ctx);
    cudaGetSymbolAddress((void**)&hid,    g_hidden);
    cudaGetSymbolAddress((void**)&h2,     g_h2);
    cudaGetSymbolAddress((void**)&act,    g_act);
    cudaGetSymbolAddress((void**)&ct,     g_cos);
    cudaGetSymbolAddress((void**)&st,     g_sin);
    cudaGetSymbolAddress((void**)&dinv,   g_inv);
    cudaGetSymbolAddress((void**)&gm,     g_mask);
    cudaGetSymbolAddress((void**)&wqh,    g_wqh);
    cudaGetSymbolAddress((void**)&wkh,    g_wkh);
    cudaGetSymbolAddress((void**)&wvh,    g_wvh);
    cudaGetSymbolAddress((void**)&woh,    g_woh);
    cudaGetSymbolAddress((void**)&wgh,    g_wgh);
    cudaGetSymbolAddress((void**)&wuh,    g_wuh);
    cudaGetSymbolAddress((void**)&wdh,    g_wdh);

    cudaFuncSetAttribute(flash_tc_kernel, cudaFuncAttributeMaxDynamicSharedMemorySize,
                         FL_BYTES);
    cudaFuncSetAttribute(mma_gemm_kernel, cudaFuncAttributeMaxDynamicSharedMemorySize,
                         G2_SMEM_BYTES);
    cudaFuncSetAttribute(qkv_gemm_kernel, cudaFuncAttributeMaxDynamicSharedMemorySize,
                         G2_SMEM_BYTES);
    cudaFuncSetAttribute(dual_gemm_silu_kernel, cudaFuncAttributeMaxDynamicSharedMemorySize,
                         M3_SMEM_BYTES);

    CvtArgs ca;
    ca.src[0] = w_q;    ca.dst[0] = wqh;
    ca.src[1] = w_k;    ca.dst[1] = wkh;
    ca.src[2] = w_v;    ca.dst[2] = wvh;
    ca.src[3] = w_o;    ca.dst[3] = woh;
    ca.src[4] = w_gate; ca.dst[4] = wgh;
    ca.src[5] = w_up;   ca.dst[5] = wuh;
    ca.src[6] = w_down; ca.dst[6] = wdh;
    ca.end[0] = 4096;
    ca.end[1] = 4096 + 2048;
    ca.end[2] = 4096 + 2048 + 2048;
    ca.end[3] = 4096 + 2048 + 2048 + 4096;
    ca.end[4] = 4096 + 2048 + 2048 + 4096 + 12288;
    ca.end[5] = 4096 + 2048 + 2048 + 4096 + 12288 + 12288;
    ca.end[6] = 4096 + 2048 + 2048 + 4096 + 12288 + 12288 + 12288;

    // #1..#3
    convert_all_kernel<<<ca.end[6], 256>>>(ca);
    rmsnorm2_kernel<<<SQ + SKK, 256>>>(hidden_states, hnorm, kv_hidden, hknorm, ln1, DM);
    rope_inv_kernel<<<1, 64>>>(dinv);
    // #4 <- profiled: merged QKV projection (320 exact-packed CTAs)
    qkv_gemm_kernel<<<320, 256, G2_SMEM_BYTES>>>(
        hnorm, hknorm, wqh, wkh, wvh, qh, kh, vh);

    rope_table_kernel<<<TT, 64>>>(dinv, ct, st);
    gather_mask_kernel<<<dim3(SKK / 256, SQ), 256>>>(causal_mask, hs_idxs, key_idxs, gm);

    qknorm_rope_kernel<<<SQ * NH / 4, 512>>>(qh, q_nw, positions, ct, st, NH);
    qknorm_rope_kernel<<<SKK * NKV / 4, 512>>>(kh, k_nw, kv_positions, ct, st, NKV);

    // BQ=128 GQA-paired flash (materialized gm): grid (16, 8) = 128 CTAs
    flash_tc_kernel<<<dim3(SQ / 128, NKV), 256, FL_BYTES>>>(qh, kh, vh, gm, ctx);

    mma_gemm_kernel<<<dim3(DM / 128, SQ / 256), 256, G2_SMEM_BYTES>>>(
        ctx, woh, hidden_states, hid, nullptr, SQ, DM, 2048, 1);

    rmsnorm_kernel<<<SQ, 256>>>(hid, ln2, h2, DM);

    dual_gemm_silu_kernel<<<dim3(FF / 128, SQ / 128), 256, M3_SMEM_BYTES>>>(
        h2, wgh, wuh, act, SQ, FF, DM);
    mma_gemm_kernel<<<dim3(DM / 128, SQ / 256), 256, G2_SMEM_BYTES>>>(
        act, wdh, hid, out, nullptr, SQ, DM, FF, 1);
}

// round 16
// speedup vs baseline: 1.1437x; 1.0103x over previous
#include <cuda_runtime.h>
#include <cuda_fp16.h>
#include <math.h>
#include <stdint.h>

// Problem dims (fixed)
#define SQ   2048
#define SKK  3072
#define TT   4096
#define DM   2048
#define NH   16
#define NKV  8
#define HD   128
#define FF   6144

// ---------------------------------------------------------------------------
// Helpers
// ---------------------------------------------------------------------------
__device__ __forceinline__ uint32_t smem_u32(const void* p) {
    uint32_t a;
    asm("{ .reg .u64 t; cvta.to.shared.u64 t, %1; cvt.u32.u64 %0, t; }" : "=r"(a) : "l"(p));
    return a;
}
__device__ __forceinline__ void cp_async16(uint32_t dst, const void* src) {
    asm volatile("cp.async.cg.shared.global [%0], [%1], 16;" :: "r"(dst), "l"(src));
}
#define CP_COMMIT() asm volatile("cp.async.commit_group;" ::: "memory")
#define CP_WAIT1()  asm volatile("cp.async.wait_group 1;" ::: "memory")
#define CP_WAIT0()  asm volatile("cp.async.wait_group 0;" ::: "memory")

// m16n8k16 fp16 mma with fp32 accumulate
__device__ __forceinline__ void mma_f16(float* d, const uint32_t* a, const uint32_t* b) {
    asm volatile(
        "mma.sync.aligned.m16n8k16.row.col.f32.f16.f16.f32 "
        "{%0,%1,%2,%3}, {%4,%5,%6,%7}, {%8,%9}, {%0,%1,%2,%3};"
        : "+f"(d[0]), "+f"(d[1]), "+f"(d[2]), "+f"(d[3])
        : "r"(a[0]), "r"(a[1]), "r"(a[2]), "r"(a[3]), "r"(b[0]), "r"(b[1]));
}
__device__ __forceinline__ void ldsm_x4(uint32_t* q, uint32_t addr) {
    asm volatile("ldmatrix.sync.aligned.m8n8.x4.shared.b16 {%0,%1,%2,%3}, [%4];"
        : "=r"(q[0]), "=r"(q[1]), "=r"(q[2]), "=r"(q[3]) : "r"(addr));
}
__device__ __forceinline__ void ldsm_x4_trans(uint32_t* q, uint32_t addr) {
    asm volatile("ldmatrix.sync.aligned.m8n8.x4.trans.shared.b16 {%0,%1,%2,%3}, [%4];"
        : "=r"(q[0]), "=r"(q[1]), "=r"(q[2]), "=r"(q[3]) : "r"(addr));
}

// ---------------------------------------------------------------------------
// Scratch
// ---------------------------------------------------------------------------
__device__ __half g_hnorm [SQ  * DM];
__device__ __half g_hknorm[SKK * DM];
__device__ __half g_qh    [SQ  * NH  * HD];
__device__ __half g_kh    [SKK * NKV * HD];
__device__ __half g_vh    [SKK * NKV * HD];
__device__ __half g_ctx   [SQ  * NH  * HD];
__device__ float  g_hidden[SQ  * DM];
__device__ __half g_h2    [SQ  * DM];
__device__ __half g_act   [SQ  * FF];
__device__ float  g_cos   [TT * 64];
__device__ float  g_sin   [TT * 64];
__device__ double g_inv   [64];
__device__ float  g_mask  [(size_t)SQ * SKK];
__device__ __half g_wqh[2048 * 2048];
__device__ __half g_wkh[2048 * 1024];
__device__ __half g_wvh[2048 * 1024];
__device__ __half g_woh[2048 * 2048];
__device__ __half g_wgh[2048 * 6144];
__device__ __half g_wuh[2048 * 6144];
__device__ __half g_wdh[6144 * 2048];

// ---------------------------------------------------------------------------
// Merged f32 -> f16 convert over all 7 weight tensors (one launch)
// ---------------------------------------------------------------------------
struct CvtArgs {
    const float* src[7];
    __half* dst[7];
    int end[7];
};
__global__ void convert_all_kernel(CvtArgs a) {
    int b = blockIdx.x;
    int j = 0, base = 0;
#pragma unroll
    for (int t = 0; t < 6; t++)
        if (b >= a.end[t]) { j = t + 1; base = a.end[t]; }
    int i = (b - base) * 256 + threadIdx.x;
    float4 v = ((const float4*)a.src[j])[i];
    ((__half2*)a.dst[j])[2 * i]     = __floats2half2_rn(v.x, v.y);
    ((__half2*)a.dst[j])[2 * i + 1] = __floats2half2_rn(v.z, v.w);
}

// ---------------------------------------------------------------------------
// Gather mask: gm[q][k] = mask[hs_idxs[q]*TT + key_idxs[k]]
// ---------------------------------------------------------------------------
__global__ void gather_mask_kernel(const float* __restrict__ mask,
                                   const int* __restrict__ hs,
                                   const int* __restrict__ ki,
                                   float* __restrict__ gm) {
    int q = blockIdx.y;
    int k = blockIdx.x * 256 + threadIdx.x;
    gm[(size_t)q * SKK + k] = __ldg(mask + (size_t)hs[q] * TT + ki[k]);
}

// ---------------------------------------------------------------------------
// RoPE tables (fp64; pow hoisted)
// ---------------------------------------------------------------------------
__global__ void rope_inv_kernel(double* __restrict__ inv) {
    int d = threadIdx.x;
    inv[d] = pow(1.0e6, -((double)(2 * d)) / 128.0);
}
__global__ void rope_table_kernel(const double* __restrict__ inv,
                                  float* __restrict__ ct, float* __restrict__ st) {
    int p = blockIdx.x;
    int d = threadIdx.x;
    double ang = (double)p * inv[d];
    ct[p * 64 + d] = (float)cos(ang);
    st[p * 64 + d] = (float)sin(ang);
}

// ---------------------------------------------------------------------------
// Row RMSNorm (dim=2048), half output. Merged variant for ln1.
// ---------------------------------------------------------------------------
__device__ __forceinline__ void rmsnorm_row(const float* xr_, const float* w,
                                            __half* yr_, int dim) {
    const float4* xr = (const float4*)xr_;
    const float4* w4 = (const float4*)w;
    __half2* yr = (__half2*)yr_;
    int n4 = dim >> 2;

    float s = 0.f;
    for (int i = threadIdx.x; i < n4; i += blockDim.x) {
        float4 v = xr[i];
        s += v.x * v.x + v.y * v.y + v.z * v.z + v.w * v.w;
    }
#pragma unroll
    for (int o = 16; o > 0; o >>= 1) s += __shfl_xor_sync(0xffffffffu, s, o);

    __shared__ float red[8];
    __shared__ float s_scale;
    int wid = threadIdx.x >> 5, lane = threadIdx.x & 31;
    if (lane == 0) red[wid] = s;
    __syncthreads();
    if (threadIdx.x == 0) {
        float t = 0.f;
        int nw = blockDim.x >> 5;
        for (int i = 0; i < nw; i++) t += red[i];
        s_scale = rsqrtf(t / (float)dim + 1e-6f);
    }
    __syncthreads();
    float sc = s_scale;
    for (int i = threadIdx.x; i < n4; i += blockDim.x) {
        float4 v = xr[i];
        float4 ww = w4[i];
        yr[2 * i]     = __floats2half2_rn(v.x * sc * ww.x, v.y * sc * ww.y);
        yr[2 * i + 1] = __floats2half2_rn(v.z * sc * ww.z, v.w * sc * ww.w);
    }
}

__global__ void rmsnorm_kernel(const float* __restrict__ x, const float* __restrict__ w,
                               __half* __restrict__ y, int dim) {
    rmsnorm_row(x + (size_t)blockIdx.x * dim, w, y + (size_t)blockIdx.x * dim, dim);
}

__global__ void rmsnorm2_kernel(const float* __restrict__ x1, __half* __restrict__ y1,
                                const float* __restrict__ x2, __half* __restrict__ y2,
                                const float* __restrict__ w, int dim) {
    int row = blockIdx.x;
    if (row < SQ)
        rmsnorm_row(x1 + (size_t)row * dim, w, y1 + (size_t)row * dim, dim);
    else {
        row -= SQ;
        rmsnorm_row(x2 + (size_t)row * dim, w, y2 + (size_t)row * dim, dim);
    }
}

// ---------------------------------------------------------------------------
// Per-head RMSNorm (D=128) + RoPE, in place on half. 4 pairs/block.
// ---------------------------------------------------------------------------
__global__ void qknorm_rope_kernel(__half* __restrict__ x,
                                   const float* __restrict__ nw,
                                   const int* __restrict__ pos,
                                   const float* __restrict__ ct, const float* __restrict__ st,
                                   int nheads) {
    int g = threadIdx.x >> 7;
    int d = threadIdx.x & 127;
    int idx = blockIdx.x * 4 + g;
    int token = idx / nheads;
    int head  = idx - token * nheads;
    __half* row = x + ((size_t)token * nheads + head) * HD;
    float v = __half2float(row[d]);

    float s = v * v;
#pragma unroll
    for (int o = 16; o > 0; o >>= 1) s += __shfl_xor_sync(0xffffffffu, s, o);
    __shared__ float wsum[4][4];
    __shared__ float xs[4][HD];
    if ((d & 31) == 0) wsum[g][d >> 5] = s;
    __syncthreads();
    float tot = wsum[g][0] + wsum[g][1] + wsum[g][2] + wsum[g][3];
    float sc = rsqrtf(tot * (1.f / 128.f) + 1e-6f);
    float xn = v * sc * nw[d];
    xs[g][d] = xn;
    __syncthreads();

    int p = pos[token];
    int j = d & 63;
    float c  = ct[p * 64 + j];
    float sn = st[p * 64 + j];
    float out;
    if (d < 64) out = xn * c - xs[g][d + 64] * sn;
    else        out = xn * c + xs[g][d - 64] * sn;
    row[d] = __float2half_rn(out);
}

// ---------------------------------------------------------------------------
// Shared GEMM tile geometry (BK=128, 2-stage, validated round 12)
// ---------------------------------------------------------------------------
#define G2_A_WORDS   (256 * 64)
#define G2_B_WORDS   (128 * 64)
#define G2_STAGE     (G2_A_WORDS + G2_B_WORDS)
#define G2_SMEM_BYTES (2 * G2_STAGE * 4)

// Generic GEMM: mode 0: C=acc, 1: C=acc+Res, 3: Ch=half(acc)
__global__ void __launch_bounds__(256, 1) mma_gemm_kernel(
    const __half* __restrict__ A, const __half* __restrict__ BT,
    const float* __restrict__ Res,
    float* __restrict__ C, __half* __restrict__ Ch,
    int M, int N, int K, int mode) {
    extern __shared__ float sm[];
    const int tid = threadIdx.x;
    const int lane = tid & 31;
    const int wid = tid >> 5;
    const int warp_m = wid & 3;
    const int warp_n = wid >> 2;
    const int grp = lane >> 2;
    const int tg = lane & 3;
    const int g1 = (lane >> 3) & 1;
    const int g2 = lane >> 4;
    const int r8 = lane & 7;

    const int col0 = blockIdx.x * 128;
    const int row0 = blockIdx.y * 256;
    const __half* Abase = A + (size_t)row0 * K;
    const __half* Bbase = BT + col0;
    const int KT = K >> 7;

    float acc[4][8][4];
#pragma unroll
    for (int mt = 0; mt < 4; mt++)
#pragma unroll
        for (int nt = 0; nt < 8; nt++)
#pragma unroll
            for (int i = 0; i < 4; i++) acc[mt][nt][i] = 0.f;

    auto load_stage = [&](int stg, int kt) {
        uint32_t sa = smem_u32(sm + stg * G2_STAGE);
        uint32_t sb = sa + G2_A_WORDS * 4;
#pragma unroll
        for (int i = 0; i < 16; i++) {
            int chunk = tid + i * 256;
            int m = chunk >> 4;
            int c = chunk & 15;
            int cs = c ^ (m & 7);
            cp_async16(sa + (uint32_t)(m * 256 + cs * 16),
                       Abase + (size_t)m * K + kt * 128 + c * 8);
        }
#pragma unroll
        for (int i = 0; i < 8; i++) {
            int chunk = tid + i * 256;
            int k = chunk >> 4;
            int c = chunk & 15;
            int cs = c ^ (k & 7);
            cp_async16(sb + (uint32_t)(k * 256 + cs * 16),
                       Bbase + (size_t)(kt * 128 + k) * N + c * 8);
        }
    };

    load_stage(0, 0); CP_COMMIT();
    if (KT > 1) load_stage(1, 1);
    CP_COMMIT();

    for (int kt = 0; kt < KT; kt++) {
        if (kt + 1 < KT) { CP_WAIT1(); } else { CP_WAIT0(); }
        __syncthreads();

        uint32_t sa = smem_u32(sm + (kt & 1) * G2_STAGE);
        uint32_t sb = sa + G2_A_WORDS * 4;

#pragma unroll
        for (int s = 0; s < 8; s++) {
            uint32_t bfr[8][2];
#pragma unroll
            for (int nt16 = 0; nt16 < 4; nt16++) {
                int kl = 16 * s + 8 * g1 + r8;
                int ch = (warp_n * 8 + 2 * nt16 + g2) ^ r8;
                uint32_t b4[4];
                ldsm_x4_trans(b4, sb + (uint32_t)(kl * 256 + ch * 16));
                bfr[2 * nt16][0] = b4[0];
                bfr[2 * nt16][1] = b4[1];
                bfr[2 * nt16 + 1][0] = b4[2];
                bfr[2 * nt16 + 1][1] = b4[3];
            }
#pragma unroll
            for (int mt = 0; mt < 4; mt++) {
                int ml = warp_m * 64 + mt * 16 + 8 * g1 + r8;
                int ch = (2 * s + g2) ^ r8;
                uint32_t af[4];
                ldsm_x4(af, sa + (uint32_t)(ml * 256 + ch * 16));
#pragma unroll
                for (int nt = 0; nt < 8; nt++)
                    mma_f16(acc[mt][nt], af, bfr[nt]);
            }
        }
        __syncthreads();
        if (kt + 2 < KT) { load_stage(kt & 1, kt + 2); CP_COMMIT(); }
    }

#pragma unroll
    for (int mt = 0; mt < 4; mt++) {
        int r = row0 + warp_m * 64 + mt * 16 + grp;
#pragma unroll
        for (int nt = 0; nt < 8; nt++) {
            int c = col0 + warp_n * 64 + nt * 8 + 2 * tg;
            size_t o0 = (size_t)r * N + c;
            size_t o1 = (size_t)(r + 8) * N + c;
            float2 v0 = make_float2(acc[mt][nt][0], acc[mt][nt][1]);
            float2 v1 = make_float2(acc[mt][nt][2], acc[mt][nt][3]);
            if (mode == 3) {
                *(__half2*)(Ch + o0) = __floats2half2_rn(v0.x, v0.y);
                *(__half2*)(Ch + o1) = __floats2half2_rn(v1.x, v1.y);
            } else {
                if (mode == 1) {
                    float2 r0 = *(const float2*)(Res + o0);
                    float2 r1 = *(const float2*)(Res + o1);
                    v0.x += r0.x; v0.y += r0.y;
                    v1.x += r1.x; v1.y += r1.y;
                }
                *(float2*)(C + o0) = v0;
                *(float2*)(C + o1) = v1;
            }
        }
    }
}

// ---------------------------------------------------------------------------
// Merged QKV projection: exact-packed 1D grid of 320 CTAs.
// ---------------------------------------------------------------------------
__global__ void __launch_bounds__(256, 1) qkv_gemm_kernel(
    const __half* __restrict__ hnorm, const __half* __restrict__ hknorm,
    const __half* __restrict__ wq, const __half* __restrict__ wk,
    const __half* __restrict__ wv,
    __half* __restrict__ qh, __half* __restrict__ kh, __half* __restrict__ vh) {
    extern __shared__ float sm[];
    const int tid = threadIdx.x;
    const int lane = tid & 31;
    const int wid = tid >> 5;
    const int warp_m = wid & 3;
    const int warp_n = wid >> 2;
    const int grp = lane >> 2;
    const int tg = lane & 3;
    const int g1 = (lane >> 3) & 1;
    const int g2 = lane >> 4;
    const int r8 = lane & 7;

    int b = blockIdx.x;
    const __half* A;
    const __half* B;
    __half* Out;
    int N, col0, row0;
    if (b < 128) {
        A = hnorm; B = wq; Out = qh; N = 2048;
        col0 = (b & 15) * 128; row0 = (b >> 4) * 256;
    } else if (b < 224) {
        int t = b - 128;
        A = hknorm; B = wk; Out = kh; N = 1024;
        col0 = (t & 7) * 128; row0 = (t >> 3) * 256;
    } else {
        int t = b - 224;
        A = hknorm; B = wv; Out = vh; N = 1024;
        col0 = (t & 7) * 128; row0 = (t >> 3) * 256;
    }
    const int K = DM;

    const __half* Abase = A + (size_t)row0 * K;
    const __half* Bbase = B + col0;
    const int KT = K >> 7;

    float acc[4][8][4];
#pragma unroll
    for (int mt = 0; mt < 4; mt++)
#pragma unroll
        for (int nt = 0; nt < 8; nt++)
#pragma unroll
            for (int i = 0; i < 4; i++) acc[mt][nt][i] = 0.f;

    auto load_stage = [&](int stg, int kt) {
        uint32_t sa = smem_u32(sm + stg * G2_STAGE);
        uint32_t sb = sa + G2_A_WORDS * 4;
#pragma unroll
        for (int i = 0; i < 16; i++) {
            int chunk = tid + i * 256;
            int m = chunk >> 4;
            int c = chunk & 15;
            int cs = c ^ (m & 7);
            cp_async16(sa + (uint32_t)(m * 256 + cs * 16),
                       Abase + (size_t)m * K + kt * 128 + c * 8);
        }
#pragma unroll
        for (int i = 0; i < 8; i++) {
            int chunk = tid + i * 256;
            int k = chunk >> 4;
            int c = chunk & 15;
            int cs = c ^ (k & 7);
            cp_async16(sb + (uint32_t)(k * 256 + cs * 16),
                       Bbase + (size_t)(kt * 128 + k) * N + c * 8);
        }
    };

    load_stage(0, 0); CP_COMMIT();
    load_stage(1, 1); CP_COMMIT();

    for (int kt = 0; kt < KT; kt++) {
        if (kt + 1 < KT) { CP_WAIT1(); } else { CP_WAIT0(); }
        __syncthreads();

        uint32_t sa = smem_u32(sm + (kt & 1) * G2_STAGE);
        uint32_t sb = sa + G2_A_WORDS * 4;

#pragma unroll
        for (int s = 0; s < 8; s++) {
            uint32_t bfr[8][2];
#pragma unroll
            for (int nt16 = 0; nt16 < 4; nt16++) {
                int kl = 16 * s + 8 * g1 + r8;
                int ch = (warp_n * 8 + 2 * nt16 + g2) ^ r8;
                uint32_t b4[4];
                ldsm_x4_trans(b4, sb + (uint32_t)(kl * 256 + ch * 16));
                bfr[2 * nt16][0] = b4[0];
                bfr[2 * nt16][1] = b4[1];
                bfr[2 * nt16 + 1][0] = b4[2];
                bfr[2 * nt16 + 1][1] = b4[3];
            }
#pragma unroll
            for (int mt = 0; mt < 4; mt++) {
                int ml = warp_m * 64 + mt * 16 + 8 * g1 + r8;
                int ch = (2 * s + g2) ^ r8;
                uint32_t af[4];
                ldsm_x4(af, sa + (uint32_t)(ml * 256 + ch * 16));
#pragma unroll
                for (int nt = 0; nt < 8; nt++)
                    mma_f16(acc[mt][nt], af, bfr[nt]);
            }
        }
        __syncthreads();
        if (kt + 2 < KT) { load_stage(kt & 1, kt + 2); CP_COMMIT(); }
    }

#pragma unroll
    for (int mt = 0; mt < 4; mt++) {
        int r = row0 + warp_m * 64 + mt * 16 + grp;
#pragma unroll
        for (int nt = 0; nt < 8; nt++) {
            int c = col0 + warp_n * 64 + nt * 8 + 2 * tg;
            size_t o0 = (size_t)r * N + c;
            size_t o1 = (size_t)(r + 8) * N + c;
            *(__half2*)(Out + o0) = __floats2half2_rn(acc[mt][nt][0], acc[mt][nt][1]);
            *(__half2*)(Out + o1) = __floats2half2_rn(acc[mt][nt][2], acc[mt][nt][3]);
        }
    }
}

// ---------------------------------------------------------------------------
// Fused gate+up+SiLU dual GEMM v2: BM=256, BN=64, BK=128, 2-stage.
// Warp tile 64 rows x 32 cols of BOTH matrices (acc_g + acc_u = 128 regs).
// A smem [256 m][128 k] (256B rows, c^(m&7)); Bg/Bu smem [128 k][64 n]
// (128B rows, c^(k&7)). No exchange: silu pairing is thread-local.
// ---------------------------------------------------------------------------
#define M3_A_WORDS (256 * 64)                      // 64 KB
#define M3_B_WORDS (128 * 32)                      // 16 KB each
#define M3_STAGE   (M3_A_WORDS + 2 * M3_B_WORDS)   // 24576 dwords = 96 KB
#define M3_SMEM_BYTES (2 * M3_STAGE * 4)           // 196608 bytes

__global__ void __launch_bounds__(256, 1) dual_gemm_silu_kernel(
    const __half* __restrict__ A, const __half* __restrict__ Bg,
    const __half* __restrict__ Bu, __half* __restrict__ Out,
    int M, int N, int K) {
    extern __shared__ float sm[];
    const int tid = threadIdx.x;
    const int lane = tid & 31;
    const int wid = tid >> 5;
    const int warp_m = wid & 3;       // 64-row slice
    const int warp_n = wid >> 2;      // 32-col slice (0/1)
    const int grp = lane >> 2;
    const int tg = lane & 3;
    const int g1 = (lane >> 3) & 1;
    const int g2 = lane >> 4;
    const int r8 = lane & 7;

    const int row0 = blockIdx.y * 256;
    const int col0 = blockIdx.x * 64;
    const __half* Abase = A + (size_t)row0 * K;
    const __half* Bgb = Bg + col0;
    const __half* Bub = Bu + col0;
    const int KT = K >> 7;

    float acc_g[4][4][4], acc_u[4][4][4];
#pragma unroll
    for (int mt = 0; mt < 4; mt++)
#pragma unroll
        for (int nt = 0; nt < 4; nt++)
#pragma unroll
            for (int i = 0; i < 4; i++) { acc_g[mt][nt][i] = 0.f; acc_u[mt][nt][i] = 0.f; }

    auto load_stage = [&](int stg, int kt) {
        uint32_t sa = smem_u32(sm + stg * M3_STAGE);
        uint32_t sg = sa + M3_A_WORDS * 4;
        uint32_t su = sg + M3_B_WORDS * 4;
        // A: 4096 chunks (256 rows x 16)
#pragma unroll
        for (int i = 0; i < 16; i++) {
            int chunk = tid + i * 256;
            int m = chunk >> 4;
            int c = chunk & 15;
            int cs = c ^ (m & 7);
            cp_async16(sa + (uint32_t)(m * 256 + cs * 16),
                       Abase + (size_t)m * K + kt * 128 + c * 8);
        }
        // Bg: 1024 chunks (128 k-rows x 8)
#pragma unroll
        for (int i = 0; i < 4; i++) {
            int chunk = tid + i * 256;
            int k = chunk >> 3;
            int c = chunk & 7;
            int cs = c ^ (k & 7);
            cp_async16(sg + (uint32_t)(k * 128 + cs * 16),
                       Bgb + (size_t)(kt * 128 + k) * N + c * 8);
        }
        // Bu: 1024 chunks
#pragma unroll
        for (int i = 0; i < 4; i++) {
            int chunk = tid + i * 256;
            int k = chunk >> 3;
            int c = chunk & 7;
            int cs = c ^ (k & 7);
            cp_async16(su + (uint32_t)(k * 128 + cs * 16),
                       Bub + (size_t)(kt * 128 + k) * N + c * 8);
        }
    };

    load_stage(0, 0); CP_COMMIT();
    if (KT > 1) load_stage(1, 1);
    CP_COMMIT();

    for (int kt = 0; kt < KT; kt++) {
        if (kt + 1 < KT) { CP_WAIT1(); } else { CP_WAIT0(); }
        __syncthreads();

        uint32_t sa = smem_u32(sm + (kt & 1) * M3_STAGE);
        uint32_t sg = sa + M3_A_WORDS * 4;
        uint32_t su = sg + M3_B_WORDS * 4;

#pragma unroll
        for (int s = 0; s < 8; s++) {
            // A fragments (4 mt)
            uint32_t af[4][4];
#pragma unroll
            for (int mt = 0; mt < 4; mt++) {
                int ml = warp_m * 64 + mt * 16 + 8 * g1 + r8;
                int ch = (2 * s + g2) ^ r8;
                ldsm_x4(af[mt], sa + (uint32_t)(ml * 256 + ch * 16));
            }
            // Bg fragments (2 x ldsm.x4 -> 4 nt)
            uint32_t bg[4][2], bu[4][2];
#pragma unroll
            for (int nt16 = 0; nt16 < 2; nt16++) {
                int kl = 16 * s + 8 * g1 + r8;
                int ch = (warp_n * 4 + 2 * nt16 + g2) ^ r8;
                uint32_t b4[4];
                ldsm_x4_trans(b4, sg + (uint32_t)(kl * 128 + ch * 16));
                bg[2 * nt16][0] = b4[0]; bg[2 * nt16][1] = b4[1];
                bg[2 * nt16 + 1][0] = b4[2]; bg[2 * nt16 + 1][1] = b4[3];
                ldsm_x4_trans(b4, su + (uint32_t)(kl * 128 + ch * 16));
                bu[2 * nt16][0] = b4[0]; bu[2 * nt16][1] = b4[1];
                bu[2 * nt16 + 1][0] = b4[2]; bu[2 * nt16 + 1][1] = b4[3];
            }
#pragma unroll
            for (int mt = 0; mt < 4; mt++)
#pragma unroll
                for (int nt = 0; nt < 4; nt++) {
                    mma_f16(acc_g[mt][nt], af[mt], bg[nt]);
                    mma_f16(acc_u[mt][nt], af[mt], bu[nt]);
                }
        }
        __syncthreads();
        if (kt + 2 < KT) { load_stage(kt & 1, kt + 2); CP_COMMIT(); }
    }

#pragma unroll
    for (int mt = 0; mt < 4; mt++) {
        int r = row0 + warp_m * 64 + mt * 16 + grp;
#pragma unroll
        for (int nt = 0; nt < 4; nt++) {
            int c = col0 + warp_n * 32 + nt * 8 + 2 * tg;
            float gx = acc_g[mt][nt][0], gy = acc_g[mt][nt][1];
            float gz = acc_g[mt][nt][2], gw = acc_g[mt][nt][3];
            *(__half2*)(Out + (size_t)r * N + c) = __floats2half2_rn(
                gx / (1.f + expf(-gx)) * acc_u[mt][nt][0],
                gy / (1.f + expf(-gy)) * acc_u[mt][nt][1]);
            *(__half2*)(Out + (size_t)(r + 8) * N + c) = __floats2half2_rn(
                gz / (1.f + expf(-gz)) * acc_u[mt][nt][2],
                gw / (1.f + expf(-gw)) * acc_u[mt][nt][3]);
        }
    }
}

// ---------------------------------------------------------------------------
// FP16 flash attention, GQA-paired, BQ=128, materialized mask (gm).
// Grid (SQ/128, NKV) = 128 CTAs. (Round-13 validated version.)
// ---------------------------------------------------------------------------
#define FL_TILES (SKK / 64)
#define FLH_QS   0
#define FLH_KS   16384
#define FLH_VT   24576
#define FLH_PS   32768
#define FLH_PH   40960
#define FLH_MI   45056
#define FLH_LI   45312
#define FLH_CORR 45568
#define FL_BYTES ((45568 + 256) * 4)

__global__ void __launch_bounds__(256, 1) flash_tc_kernel(
    const __half* __restrict__ Q, const __half* __restrict__ Kg,
    const __half* __restrict__ Vg, const float* __restrict__ gm,
    __half* __restrict__ ctx) {
    extern __shared__ float sm[];
    float* Qs = sm + FLH_QS;
    float* Ks = sm + FLH_KS;
    float* Vt = sm + FLH_VT;
    float* Ps = sm + FLH_PS;
    float* Ph = sm + FLH_PH;
    float* mi = sm + FLH_MI;
    float* li = sm + FLH_LI;
    float* corr = sm + FLH_CORR;

    const int tid = threadIdx.x;
    const int lane = tid & 31;
    const int wrp = tid >> 5;
    const int warp_m = wrp & 3;
    const int warp_n = wrp >> 2;
    const int grp = lane >> 2;
    const int tg = lane & 3;
    const int q0 = blockIdx.x << 7;
    const int hk = blockIdx.y;
    const int h0 = hk << 1;

    const float scale = 0.08838834764831845f;
    const float LOG2E = 1.44269504088896340736f;

#pragma unroll
    for (int i = 0; i < 16; i++) {
        int chunk = tid + i * 256;
        int hh = chunk >> 11;
        int rc = chunk & 2047;
        int row = rc >> 4;
        int jc = rc & 15;
        int c = jc >> 3, j = jc & 7;
        int pj = (j + 2 * (row & 3)) & 7;
        cp_async16(smem_u32(Qs + hh * 8192 + (c * 128 + row) * 32 + pj * 4),
                   Q + (size_t)(q0 + row) * (NH * HD) + (h0 + hh) * HD + jc * 8);
    }
#pragma unroll
    for (int i = 0; i < 4; i++) {
        int chunk = tid + i * 256;
        int row = chunk >> 4;
        int jc = chunk & 15;
        int c = jc >> 3, j = jc & 7;
        int pj = (j + 2 * (row & 3)) & 7;
        cp_async16(smem_u32(Ks + (c * 64 + row) * 32 + pj * 4),
                   Kg + (size_t)row * (NKV * HD) + hk * HD + jc * 8);
    }
    CP_COMMIT();

    mi[tid] = -INFINITY;
    li[tid] = 0.f;

    float acc_o[2][2][8][4];
#pragma unroll
    for (int hh = 0; hh < 2; hh++)
#pragma unroll
        for (int mt = 0; mt < 2; mt++)
#pragma unroll
            for (int nt = 0; nt < 8; nt++)
#pragma unroll
                for (int i = 0; i < 4; i++) acc_o[hh][mt][nt][i] = 0.f;

    const int jp = tid & 31;
    const int dbase = (tid >> 5) * 16;
    uint4 vra[2], vrb[2];
    {
        const __half* pa = Vg + (size_t)(2 * jp) * (NKV * HD) + hk * HD + dbase;
        const __half* pb = Vg + (size_t)(2 * jp + 1) * (NKV * HD) + hk * HD + dbase;
        vra[0] = *(const uint4*)pa; vra[1] = *(const uint4*)(pa + 8);
        vrb[0] = *(const uint4*)pb; vrb[1] = *(const uint4*)(pb + 8);
    }

    for (int kt = 0; kt < FL_TILES; kt++) {
        const int buf = kt & 1;
        const int k0 = kt << 6;
        const float* KsB = Ks + buf * 4096;
        const float* VtB = Vt + buf * 4096;

        __syncthreads();   // (a)

        {
            float* VtW = Vt + buf * 4096;
            const __half* ha = (const __half*)vra;
            const __half* hb = (const __half*)vrb;
            int j = jp >> 2, kin = jp & 3;
#pragma unroll
            for (int d = 0; d < 16; d++) {
                int row = dbase + d;
                int pj = (j + 2 * (row & 3)) & 7;
                *(__half2*)(VtW + row * 32 + pj * 4 + kin) =
                    __halves2half2(ha[d], hb[d]);
            }
        }
        if (kt + 1 < FL_TILES) {
            int k0n = k0 + 64;
#pragma unroll
            for (int i = 0; i < 4; i++) {
                int chunk = tid + i * 256;
                int row = chunk >> 4;
                int jc = chunk & 15;
                int c = jc >> 3, j = jc & 7;
                int pj = (j + 2 * (row & 3)) & 7;
                cp_async16(smem_u32(Ks + (buf ^ 1) * 4096 + (c * 64 + row) * 32 + pj * 4),
                           Kg + (size_t)(k0n + row) * (NKV * HD) + hk * HD + jc * 8);
            }
            CP_COMMIT();
            const __half* pa = Vg + (size_t)(k0n + 2 * jp) * (NKV * HD) + hk * HD + dbase;
            const __half* pb = Vg + (size_t)(k0n + 2 * jp + 1) * (NKV * HD) + hk * HD + dbase;
            vra[0] = *(const uint4*)pa; vra[1] = *(const uint4*)(pa + 8);
            vrb[0] = *(const uint4*)pb; vrb[1] = *(const uint4*)(pb + 8);
            CP_WAIT1();
        } else {
            CP_WAIT0();
        }
        __syncthreads();   // (b)

#pragma unroll
        for (int hh = 0; hh < 2; hh++) {
            const float* QsH = Qs + hh * 8192;

            float accs[2][4][4];
#pragma unroll
            for (int mt = 0; mt < 2; mt++)
#pragma unroll
                for (int nt = 0; nt < 4; nt++)
#pragma unroll
                    for (int i = 0; i < 4; i++) accs[mt][nt][i] = 0.f;
#pragma unroll
            for (int c = 0; c < 2; c++)
#pragma unroll
                for (int s = 0; s < 4; s++) {
                    int off = 2 * ((4 * s + tg + 4 * (grp & 3)) & 15);
                    uint32_t bf[4][2];
#pragma unroll
                    for (int nt = 0; nt < 4; nt++) {
                        int rb = warp_n * 32 + nt * 8 + grp;
                        float2 bv = *(const float2*)(KsB + (c * 64 + rb) * 32 + off);
                        bf[nt][0] = __float_as_uint(bv.x);
                        bf[nt][1] = __float_as_uint(bv.y);
                    }
#pragma unroll
                    for (int mt = 0; mt < 2; mt++) {
                        int rm = warp_m * 32 + mt * 16 + grp;
                        const float* ab = QsH + (c * 128 + rm) * 32 + off;
                        float2 pa = *(const float2*)ab;
                        float2 qa = *(const float2*)(ab + 8 * 32);
                        uint32_t af[4] = {__float_as_uint(pa.x), __float_as_uint(qa.x),
                                          __float_as_uint(pa.y), __float_as_uint(qa.y)};
#pragma unroll
                        for (int nt = 0; nt < 4; nt++)
                            mma_f16(accs[mt][nt], af, bf[nt]);
                    }
                }

#pragma unroll
            for (int mt = 0; mt < 2; mt++) {
                int r0 = warp_m * 32 + mt * 16 + grp, r1 = r0 + 8;
                const float* g0 = gm + (size_t)(q0 + r0) * SKK + k0;
                const float* g1 = gm + (size_t)(q0 + r1) * SKK + k0;
#pragma unroll
                for (int nt = 0; nt < 4; nt++) {
                    int cn = warp_n * 32 + nt * 8 + 2 * tg;
                    float2 m0 = *(const float2*)(g0 + cn);
                    float2 m1 = *(const float2*)(g1 + cn);
                    int c = cn >> 5, k32 = cn & 31;
                    int pj = ((k32 >> 2) + 2 * (r0 & 3)) & 7;
                    int kin = k32 & 3;
                    float2 o0 = make_float2(accs[mt][nt][0] * scale + m0.x,
                                            accs[mt][nt][1] * scale + m0.y);
                    float2 o1 = make_float2(accs[mt][nt][2] * scale + m1.x,
                                            accs[mt][nt][3] * scale + m1.y);
                    *(float2*)(Ps + (c * 128 + r0) * 32 + pj * 4 + kin) = o0;
                    *(float2*)(Ps + (c * 128 + r1) * 32 + pj * 4 + kin) = o1;
                }
            }
            __syncthreads();   // (c)

            {
                int row = tid >> 1, c = tid & 1;
                const float* base = Ps + (c * 128 + row) * 32;
                float4 v[8];
#pragma unroll
                for (int jj = 0; jj < 8; jj++) {
                    int pjs = (jj + 2 * (row & 3)) & 7;
                    v[jj] = *(const float4*)(base + pjs * 4);
                }
                float m_old = mi[hh * 128 + row];
                float m = m_old;
#pragma unroll
                for (int jj = 0; jj < 8; jj++)
                    m = fmaxf(m, fmaxf(fmaxf(v[jj].x, v[jj].y), fmaxf(v[jj].z, v[jj].w)));
                m = fmaxf(m, __shfl_xor_sync(0xffffffffu, m, 1));
                float l = 0.f;
#pragma unroll
                for (int jj = 0; jj < 8; jj++) {
                    float px = exp2f((v[jj].x - m) * LOG2E);
                    float py = exp2f((v[jj].y - m) * LOG2E);
                    float pz = exp2f((v[jj].z - m) * LOG2E);
                    float pw = exp2f((v[jj].w - m) * LOG2E);
                    l += (px + py) + (pz + pw);
                    int ck0 = c * 16 + jj * 2;
#pragma unroll
                    for (int p = 0; p < 2; p++) {
                        int ck = ck0 + p;
                        int jh = ck >> 2, kinh = ck & 3;
                        int pjh = (jh + 2 * (row & 3)) & 7;
                        __half2 hv = (p == 0) ? __floats2half2_rn(px, py)
                                              : __floats2half2_rn(pz, pw);
                        *(__half2*)(Ph + row * 32 + pjh * 4 + kinh) = hv;
                    }
                }
                l += __shfl_xor_sync(0xffffffffu, l, 1);
                if (c == 0) {
                    float cr = exp2f((m_old - m) * LOG2E);
                    corr[hh * 128 + row] = cr;
                    li[hh * 128 + row] = li[hh * 128 + row] * cr + l;
                    mi[hh * 128 + row] = m;
                }
            }
            __syncthreads();   // (d)

            {
#pragma unroll
                for (int mt = 0; mt < 2; mt++) {
                    int rm = warp_m * 32 + mt * 16 + grp;
                    float cr0 = corr[hh * 128 + rm];
                    float cr1 = corr[hh * 128 + rm + 8];
#pragma unroll
                    for (int nt = 0; nt < 8; nt++) {
                        acc_o[hh][mt][nt][0] *= cr0; acc_o[hh][mt][nt][1] *= cr0;
                        acc_o[hh][mt][nt][2] *= cr1; acc_o[hh][mt][nt][3] *= cr1;
                    }
                }
#pragma unroll
                for (int s = 0; s < 4; s++) {
                    int off = 2 * ((4 * s + tg + 4 * (grp & 3)) & 15);
                    uint32_t bf[8][2];
#pragma unroll
                    for (int nt = 0; nt < 8; nt++) {
                        int rb = warp_n * 64 + nt * 8 + grp;
                        float2 bv = *(const float2*)(VtB + rb * 32 + off);
                        bf[nt][0] = __float_as_uint(bv.x);
                        bf[nt][1] = __float_as_uint(bv.y);
                    }
#pragma unroll
                    for (int mt = 0; mt < 2; mt++) {
                        int rm = warp_m * 32 + mt * 16 + grp;
                        float2 pa = *(const float2*)(Ph + rm * 32 + off);
                        float2 qa = *(const float2*)(Ph + (rm + 8) * 32 + off);
                        uint32_t af[4] = {__float_as_uint(pa.x), __float_as_uint(qa.x),
                                          __float_as_uint(pa.y), __float_as_uint(qa.y)};
#pragma unroll
                        for (int nt = 0; nt < 8; nt++)
                            mma_f16(acc_o[hh][mt][nt], af, bf[nt]);
                    }
                }
            }
        }
    }

#pragma unroll
    for (int hh = 0; hh < 2; hh++)
#pragma unroll
        for (int mt = 0; mt < 2; mt++) {
            int lr0 = warp_m * 32 + mt * 16 + grp;
            float inv0 = 1.f / li[hh * 128 + lr0];
            float inv1 = 1.f / li[hh * 128 + lr0 + 8];
            __half* p0 = ctx + (size_t)(q0 + lr0) * (NH * HD) + (h0 + hh) * HD;
            __half* p1 = ctx + (size_t)(q0 + lr0 + 8) * (NH * HD) + (h0 + hh) * HD;
#pragma unroll
            for (int nt = 0; nt < 8; nt++) {
                int col = warp_n * 64 + nt * 8 + 2 * tg;
                *(__half2*)(p0 + col) = __floats2half2_rn(acc_o[hh][mt][nt][0] * inv0,
                                                          acc_o[hh][mt][nt][1] * inv0);
                *(__half2*)(p1 + col) = __floats2half2_rn(acc_o[hh][mt][nt][2] * inv1,
                                                          acc_o[hh][mt][nt][3] * inv1);
            }
        }
}

// ---------------------------------------------------------------------------
// Launch sequence. Profiled launch = #4: merged QKV GEMM.
// ---------------------------------------------------------------------------
extern "C" void kernel_launch(void* const* d_in, const int* in_sizes, int n_in,
                              void* d_out, int out_size) {
    const float* hidden_states = (const float*)d_in[0];
    const float* kv_hidden     = (const float*)d_in[1];
    const float* causal_mask   = (const float*)d_in[2];
    const float* w_q    = (const float*)d_in[3];
    const float* w_k    = (const float*)d_in[4];
    const float* w_v    = (const float*)d_in[5];
    const float* w_o    = (const float*)d_in[6];
    const float* q_nw   = (const float*)d_in[7];
    const float* k_nw   = (const float*)d_in[8];
    const float* ln1    = (const float*)d_in[9];
    const float* ln2    = (const float*)d_in[10];
    const float* w_gate = (const float*)d_in[11];
    const float* w_up   = (const float*)d_in[12];
    const float* w_down = (const float*)d_in[13];
    const int* positions    = (const int*)d_in[14];
    const int* kv_positions = (const int*)d_in[15];
    const int* hs_idxs      = (const int*)d_in[16];
    const int* key_idxs     = (const int*)d_in[17];
    float* out = (float*)d_out;

    __half *hnorm, *hknorm, *qh, *kh, *vh, *ctx, *h2, *act;
    float *hid, *ct, *st, *gm;
    double* dinv;
    __half *wqh, *wkh, *wvh, *woh, *wgh, *wuh, *wdh;
    cudaGetSymbolAddress((void**)&hnorm,  g_hnorm);
    cudaGetSymbolAddress((void**)&hknorm, g_hknorm);
    cudaGetSymbolAddress((void**)&qh,     g_qh);
    cudaGetSymbolAddress((void**)&kh,     g_kh);
    cudaGetSymbolAddress((void**)&vh,     g_vh);
    cudaGetSymbolAddress((void**)&ctx,    g_ctx);
    cudaGetSymbolAddress((void**)&hid,    g_hidden);
    cudaGetSymbolAddress((void**)&h2,     g_h2);
    cudaGetSymbolAddress((void**)&act,    g_act);
    cudaGetSymbolAddress((void**)&ct,     g_cos);
    cudaGetSymbolAddress((void**)&st,     g_sin);
    cudaGetSymbolAddress((void**)&dinv,   g_inv);
    cudaGetSymbolAddress((void**)&gm,     g_mask);
    cudaGetSymbolAddress((void**)&wqh,    g_wqh);
    cudaGetSymbolAddress((void**)&wkh,    g_wkh);
    cudaGetSymbolAddress((void**)&wvh,    g_wvh);
    cudaGetSymbolAddress((void**)&woh,    g_woh);
    cudaGetSymbolAddress((void**)&wgh,    g_wgh);
    cudaGetSymbolAddress((void**)&wuh,    g_wuh);
    cudaGetSymbolAddress((void**)&wdh,    g_wdh);

    cudaFuncSetAttribute(flash_tc_kernel, cudaFuncAttributeMaxDynamicSharedMemorySize,
                         FL_BYTES);
    cudaFuncSetAttribute(mma_gemm_kernel, cudaFuncAttributeMaxDynamicSharedMemorySize,
                         G2_SMEM_BYTES);
    cudaFuncSetAttribute(qkv_gemm_kernel, cudaFuncAttributeMaxDynamicSharedMemorySize,
                         G2_SMEM_BYTES);
    cudaFuncSetAttribute(dual_gemm_silu_kernel, cudaFuncAttributeMaxDynamicSharedMemorySize,
                         M3_SMEM_BYTES);

    CvtArgs ca;
    ca.src[0] = w_q;    ca.dst[0] = wqh;
    ca.src[1] = w_k;    ca.dst[1] = wkh;
    ca.src[2] = w_v;    ca.dst[2] = wvh;
    ca.src[3] = w_o;    ca.dst[3] = woh;
    ca.src[4] = w_gate; ca.dst[4] = wgh;
    ca.src[5] = w_up;   ca.dst[5] = wuh;
    ca.src[6] = w_down; ca.dst[6] = wdh;
    ca.end[0] = 4096;
    ca.end[1] = 4096 + 2048;
    ca.end[2] = 4096 + 2048 + 2048;
    ca.end[3] = 4096 + 2048 + 2048 + 4096;
    ca.end[4] = 4096 + 2048 + 2048 + 4096 + 12288;
    ca.end[5] = 4096 + 2048 + 2048 + 4096 + 12288 + 12288;
    ca.end[6] = 4096 + 2048 + 2048 + 4096 + 12288 + 12288 + 12288;

    // #1..#3
    convert_all_kernel<<<ca.end[6], 256>>>(ca);
    rmsnorm2_kernel<<<SQ + SKK, 256>>>(hidden_states, hnorm, kv_hidden, hknorm, ln1, DM);
    rope_inv_kernel<<<1, 64>>>(dinv);
    // #4 <- profiled: merged QKV projection (320 exact-packed CTAs)
    qkv_gemm_kernel<<<320, 256, G2_SMEM_BYTES>>>(
        hnorm, hknorm, wqh, wkh, wvh, qh, kh, vh);

    rope_table_kernel<<<TT, 64>>>(dinv, ct, st);
    gather_mask_kernel<<<dim3(SKK / 256, SQ), 256>>>(causal_mask, hs_idxs, key_idxs, gm);

    qknorm_rope_kernel<<<SQ * NH / 4, 512>>>(qh, q_nw, positions, ct, st, NH);
    qknorm_rope_kernel<<<SKK * NKV / 4, 512>>>(kh, k_nw, kv_positions, ct, st, NKV);

    // BQ=128 GQA-paired flash (materialized gm)
    flash_tc_kernel<<<dim3(SQ / 128, NKV), 256, FL_BYTES>>>(qh, kh, vh, gm, ctx);

    mma_gemm_kernel<<<dim3(DM / 128, SQ / 256), 256, G2_SMEM_BYTES>>>(
        ctx, woh, hidden_states, hid, nullptr, SQ, DM, 2048, 1);

    rmsnorm_kernel<<<SQ, 256>>>(hid, ln2, h2, DM);

    // Dual gate+up+silu v2: BM=256 x BN=64, grid (96, 8)
    dual_gemm_silu_kernel<<<dim3(FF / 64, SQ / 256), 256, M3_SMEM_BYTES>>>(
        h2, wgh, wuh, act, SQ, FF, DM);
    mma_gemm_kernel<<<dim3(DM / 128, SQ / 256), 256, G2_SMEM_BYTES>>>(
        act, wdh, hid, out, nullptr, SQ, DM, FF, 1);
}

// round 17
// speedup vs baseline: 1.1593x; 1.0136x over previous
#include <cuda_runtime.h>
#include <cuda_fp16.h>
#include <math.h>
#include <stdint.h>

// Problem dims (fixed)
#define SQ   2048
#define SKK  3072
#define TT   4096
#define DM   2048
#define NH   16
#define NKV  8
#define HD   128
#define FF   6144

// ---------------------------------------------------------------------------
// Helpers
// ---------------------------------------------------------------------------
__device__ __forceinline__ uint32_t smem_u32(const void* p) {
    uint32_t a;
    asm("{ .reg .u64 t; cvta.to.shared.u64 t, %1; cvt.u32.u64 %0, t; }" : "=r"(a) : "l"(p));
    return a;
}
__device__ __forceinline__ void cp_async16(uint32_t dst, const void* src) {
    asm volatile("cp.async.cg.shared.global [%0], [%1], 16;" :: "r"(dst), "l"(src));
}
#define CP_COMMIT() asm volatile("cp.async.commit_group;" ::: "memory")
#define CP_WAIT1()  asm volatile("cp.async.wait_group 1;" ::: "memory")
#define CP_WAIT0()  asm volatile("cp.async.wait_group 0;" ::: "memory")

// m16n8k16 fp16 mma with fp32 accumulate
__device__ __forceinline__ void mma_f16(float* d, const uint32_t* a, const uint32_t* b) {
    asm volatile(
        "mma.sync.aligned.m16n8k16.row.col.f32.f16.f16.f32 "
        "{%0,%1,%2,%3}, {%4,%5,%6,%7}, {%8,%9}, {%0,%1,%2,%3};"
        : "+f"(d[0]), "+f"(d[1]), "+f"(d[2]), "+f"(d[3])
        : "r"(a[0]), "r"(a[1]), "r"(a[2]), "r"(a[3]), "r"(b[0]), "r"(b[1]));
}
__device__ __forceinline__ void ldsm_x4(uint32_t* q, uint32_t addr) {
    asm volatile("ldmatrix.sync.aligned.m8n8.x4.shared.b16 {%0,%1,%2,%3}, [%4];"
        : "=r"(q[0]), "=r"(q[1]), "=r"(q[2]), "=r"(q[3]) : "r"(addr));
}
__device__ __forceinline__ void ldsm_x4_trans(uint32_t* q, uint32_t addr) {
    asm volatile("ldmatrix.sync.aligned.m8n8.x4.trans.shared.b16 {%0,%1,%2,%3}, [%4];"
        : "=r"(q[0]), "=r"(q[1]), "=r"(q[2]), "=r"(q[3]) : "r"(addr));
}

// ---------------------------------------------------------------------------
// Scratch
// ---------------------------------------------------------------------------
__device__ __half g_hnorm [SQ  * DM];
__device__ __half g_hknorm[SKK * DM];
__device__ __half g_qh    [SQ  * NH  * HD];
__device__ __half g_kh    [SKK * NKV * HD];
__device__ __half g_vh    [SKK * NKV * HD];
__device__ __half g_ctx   [SQ  * NH  * HD];
__device__ float  g_hidden[SQ  * DM];
__device__ __half g_h2    [SQ  * DM];
__device__ __half g_act   [SQ  * FF];
__device__ float  g_cos   [TT * 64];
__device__ float  g_sin   [TT * 64];
__device__ double g_inv   [64];
__device__ float  g_mask  [(size_t)SQ * SKK];
__device__ __half g_wqh[2048 * 2048];
__device__ __half g_wkh[2048 * 1024];
__device__ __half g_wvh[2048 * 1024];
__device__ __half g_woh[2048 * 2048];
__device__ __half g_wgh[2048 * 6144];
__device__ __half g_wuh[2048 * 6144];
__device__ __half g_wdh[6144 * 2048];

// ---------------------------------------------------------------------------
// Merged f32 -> f16 convert over all 7 weight tensors (one launch)
// ---------------------------------------------------------------------------
struct CvtArgs {
    const float* src[7];
    __half* dst[7];
    int end[7];
};
__global__ void convert_all_kernel(CvtArgs a) {
    int b = blockIdx.x;
    int j = 0, base = 0;
#pragma unroll
    for (int t = 0; t < 6; t++)
        if (b >= a.end[t]) { j = t + 1; base = a.end[t]; }
    int i = (b - base) * 256 + threadIdx.x;
    float4 v = ((const float4*)a.src[j])[i];
    ((__half2*)a.dst[j])[2 * i]     = __floats2half2_rn(v.x, v.y);
    ((__half2*)a.dst[j])[2 * i + 1] = __floats2half2_rn(v.z, v.w);
}

// ---------------------------------------------------------------------------
// Gather mask: gm[q][k] = mask[hs_idxs[q]*TT + key_idxs[k]]
// ---------------------------------------------------------------------------
__global__ void gather_mask_kernel(const float* __restrict__ mask,
                                   const int* __restrict__ hs,
                                   const int* __restrict__ ki,
                                   float* __restrict__ gm) {
    int q = blockIdx.y;
    int k = blockIdx.x * 256 + threadIdx.x;
    gm[(size_t)q * SKK + k] = __ldg(mask + (size_t)hs[q] * TT + ki[k]);
}

// ---------------------------------------------------------------------------
// RoPE tables (fp64; pow hoisted)
// ---------------------------------------------------------------------------
__global__ void rope_inv_kernel(double* __restrict__ inv) {
    int d = threadIdx.x;
    inv[d] = pow(1.0e6, -((double)(2 * d)) / 128.0);
}
__global__ void rope_table_kernel(const double* __restrict__ inv,
                                  float* __restrict__ ct, float* __restrict__ st) {
    int p = blockIdx.x;
    int d = threadIdx.x;
    double ang = (double)p * inv[d];
    ct[p * 64 + d] = (float)cos(ang);
    st[p * 64 + d] = (float)sin(ang);
}

// ---------------------------------------------------------------------------
// Row RMSNorm (dim=2048), half output. Merged variant for ln1.
// ---------------------------------------------------------------------------
__device__ __forceinline__ void rmsnorm_row(const float* xr_, const float* w,
                                            __half* yr_, int dim) {
    const float4* xr = (const float4*)xr_;
    const float4* w4 = (const float4*)w;
    __half2* yr = (__half2*)yr_;
    int n4 = dim >> 2;

    float s = 0.f;
    for (int i = threadIdx.x; i < n4; i += blockDim.x) {
        float4 v = xr[i];
        s += v.x * v.x + v.y * v.y + v.z * v.z + v.w * v.w;
    }
#pragma unroll
    for (int o = 16; o > 0; o >>= 1) s += __shfl_xor_sync(0xffffffffu, s, o);

    __shared__ float red[8];
    __shared__ float s_scale;
    int wid = threadIdx.x >> 5, lane = threadIdx.x & 31;
    if (lane == 0) red[wid] = s;
    __syncthreads();
    if (threadIdx.x == 0) {
        float t = 0.f;
        int nw = blockDim.x >> 5;
        for (int i = 0; i < nw; i++) t += red[i];
        s_scale = rsqrtf(t / (float)dim + 1e-6f);
    }
    __syncthreads();
    float sc = s_scale;
    for (int i = threadIdx.x; i < n4; i += blockDim.x) {
        float4 v = xr[i];
        float4 ww = w4[i];
        yr[2 * i]     = __floats2half2_rn(v.x * sc * ww.x, v.y * sc * ww.y);
        yr[2 * i + 1] = __floats2half2_rn(v.z * sc * ww.z, v.w * sc * ww.w);
    }
}

__global__ void rmsnorm_kernel(const float* __restrict__ x, const float* __restrict__ w,
                               __half* __restrict__ y, int dim) {
    rmsnorm_row(x + (size_t)blockIdx.x * dim, w, y + (size_t)blockIdx.x * dim, dim);
}

__global__ void rmsnorm2_kernel(const float* __restrict__ x1, __half* __restrict__ y1,
                                const float* __restrict__ x2, __half* __restrict__ y2,
                                const float* __restrict__ w, int dim) {
    int row = blockIdx.x;
    if (row < SQ)
        rmsnorm_row(x1 + (size_t)row * dim, w, y1 + (size_t)row * dim, dim);
    else {
        row -= SQ;
        rmsnorm_row(x2 + (size_t)row * dim, w, y2 + (size_t)row * dim, dim);
    }
}

// ---------------------------------------------------------------------------
// Per-head RMSNorm (D=128) + RoPE, in place on half. 4 pairs/block.
// ---------------------------------------------------------------------------
__global__ void qknorm_rope_kernel(__half* __restrict__ x,
                                   const float* __restrict__ nw,
                                   const int* __restrict__ pos,
                                   const float* __restrict__ ct, const float* __restrict__ st,
                                   int nheads) {
    int g = threadIdx.x >> 7;
    int d = threadIdx.x & 127;
    int idx = blockIdx.x * 4 + g;
    int token = idx / nheads;
    int head  = idx - token * nheads;
    __half* row = x + ((size_t)token * nheads + head) * HD;
    float v = __half2float(row[d]);

    float s = v * v;
#pragma unroll
    for (int o = 16; o > 0; o >>= 1) s += __shfl_xor_sync(0xffffffffu, s, o);
    __shared__ float wsum[4][4];
    __shared__ float xs[4][HD];
    if ((d & 31) == 0) wsum[g][d >> 5] = s;
    __syncthreads();
    float tot = wsum[g][0] + wsum[g][1] + wsum[g][2] + wsum[g][3];
    float sc = rsqrtf(tot * (1.f / 128.f) + 1e-6f);
    float xn = v * sc * nw[d];
    xs[g][d] = xn;
    __syncthreads();

    int p = pos[token];
    int j = d & 63;
    float c  = ct[p * 64 + j];
    float sn = st[p * 64 + j];
    float out;
    if (d < 64) out = xn * c - xs[g][d + 64] * sn;
    else        out = xn * c + xs[g][d - 64] * sn;
    row[d] = __float2half_rn(out);
}

// ---------------------------------------------------------------------------
// Shared GEMM tile geometry (BK=128, 2-stage, validated round 12)
// ---------------------------------------------------------------------------
#define G2_A_WORDS   (256 * 64)
#define G2_B_WORDS   (128 * 64)
#define G2_STAGE     (G2_A_WORDS + G2_B_WORDS)
#define G2_SMEM_BYTES (2 * G2_STAGE * 4)

// Generic GEMM: mode 0: C=acc, 1: C=acc+Res, 3: Ch=half(acc)
__global__ void __launch_bounds__(256, 1) mma_gemm_kernel(
    const __half* __restrict__ A, const __half* __restrict__ BT,
    const float* __restrict__ Res,
    float* __restrict__ C, __half* __restrict__ Ch,
    int M, int N, int K, int mode) {
    extern __shared__ float sm[];
    const int tid = threadIdx.x;
    const int lane = tid & 31;
    const int wid = tid >> 5;
    const int warp_m = wid & 3;
    const int warp_n = wid >> 2;
    const int grp = lane >> 2;
    const int tg = lane & 3;
    const int g1 = (lane >> 3) & 1;
    const int g2 = lane >> 4;
    const int r8 = lane & 7;

    const int col0 = blockIdx.x * 128;
    const int row0 = blockIdx.y * 256;
    const __half* Abase = A + (size_t)row0 * K;
    const __half* Bbase = BT + col0;
    const int KT = K >> 7;

    float acc[4][8][4];
#pragma unroll
    for (int mt = 0; mt < 4; mt++)
#pragma unroll
        for (int nt = 0; nt < 8; nt++)
#pragma unroll
            for (int i = 0; i < 4; i++) acc[mt][nt][i] = 0.f;

    auto load_stage = [&](int stg, int kt) {
        uint32_t sa = smem_u32(sm + stg * G2_STAGE);
        uint32_t sb = sa + G2_A_WORDS * 4;
#pragma unroll
        for (int i = 0; i < 16; i++) {
            int chunk = tid + i * 256;
            int m = chunk >> 4;
            int c = chunk & 15;
            int cs = c ^ (m & 7);
            cp_async16(sa + (uint32_t)(m * 256 + cs * 16),
                       Abase + (size_t)m * K + kt * 128 + c * 8);
        }
#pragma unroll
        for (int i = 0; i < 8; i++) {
            int chunk = tid + i * 256;
            int k = chunk >> 4;
            int c = chunk & 15;
            int cs = c ^ (k & 7);
            cp_async16(sb + (uint32_t)(k * 256 + cs * 16),
                       Bbase + (size_t)(kt * 128 + k) * N + c * 8);
        }
    };

    load_stage(0, 0); CP_COMMIT();
    if (KT > 1) load_stage(1, 1);
    CP_COMMIT();

    for (int kt = 0; kt < KT; kt++) {
        if (kt + 1 < KT) { CP_WAIT1(); } else { CP_WAIT0(); }
        __syncthreads();

        uint32_t sa = smem_u32(sm + (kt & 1) * G2_STAGE);
        uint32_t sb = sa + G2_A_WORDS * 4;

#pragma unroll
        for (int s = 0; s < 8; s++) {
            uint32_t bfr[8][2];
#pragma unroll
            for (int nt16 = 0; nt16 < 4; nt16++) {
                int kl = 16 * s + 8 * g1 + r8;
                int ch = (warp_n * 8 + 2 * nt16 + g2) ^ r8;
                uint32_t b4[4];
                ldsm_x4_trans(b4, sb + (uint32_t)(kl * 256 + ch * 16));
                bfr[2 * nt16][0] = b4[0];
                bfr[2 * nt16][1] = b4[1];
                bfr[2 * nt16 + 1][0] = b4[2];
                bfr[2 * nt16 + 1][1] = b4[3];
            }
#pragma unroll
            for (int mt = 0; mt < 4; mt++) {
                int ml = warp_m * 64 + mt * 16 + 8 * g1 + r8;
                int ch = (2 * s + g2) ^ r8;
                uint32_t af[4];
                ldsm_x4(af, sa + (uint32_t)(ml * 256 + ch * 16));
#pragma unroll
                for (int nt = 0; nt < 8; nt++)
                    mma_f16(acc[mt][nt], af, bfr[nt]);
            }
        }
        __syncthreads();
        if (kt + 2 < KT) { load_stage(kt & 1, kt + 2); CP_COMMIT(); }
    }

#pragma unroll
    for (int mt = 0; mt < 4; mt++) {
        int r = row0 + warp_m * 64 + mt * 16 + grp;
#pragma unroll
        for (int nt = 0; nt < 8; nt++) {
            int c = col0 + warp_n * 64 + nt * 8 + 2 * tg;
            size_t o0 = (size_t)r * N + c;
            size_t o1 = (size_t)(r + 8) * N + c;
            float2 v0 = make_float2(acc[mt][nt][0], acc[mt][nt][1]);
            float2 v1 = make_float2(acc[mt][nt][2], acc[mt][nt][3]);
            if (mode == 3) {
                *(__half2*)(Ch + o0) = __floats2half2_rn(v0.x, v0.y);
                *(__half2*)(Ch + o1) = __floats2half2_rn(v1.x, v1.y);
            } else {
                if (mode == 1) {
                    float2 r0 = *(const float2*)(Res + o0);
                    float2 r1 = *(const float2*)(Res + o1);
                    v0.x += r0.x; v0.y += r0.y;
                    v1.x += r1.x; v1.y += r1.y;
                }
                *(float2*)(C + o0) = v0;
                *(float2*)(C + o1) = v1;
            }
        }
    }
}

// ---------------------------------------------------------------------------
// Templated QKV tile body: BM = 64*MT rows, BN=128, BK=128, mode-3 epilogue.
// MT=4 is byte-identical to the validated big path; MT=2 is the half tile.
// Abase/Bbase/OutBase are pre-offset to (row0, col0); indices are local.
// ---------------------------------------------------------------------------
template <int MT>
__device__ __forceinline__ void qkv_tile(
    const __half* __restrict__ Abase, const __half* __restrict__ Bbase,
    __half* __restrict__ OutBase, int N, float* sm) {
    constexpr int A_WORDS = MT * 64 * 64;     // BM rows x 64 dwords
    constexpr int STAGE = A_WORDS + 128 * 64;
    const int tid = threadIdx.x;
    const int lane = tid & 31;
    const int wid = tid >> 5;
    const int warp_m = wid & 3;
    const int warp_n = wid >> 2;
    const int grp = lane >> 2;
    const int tg = lane & 3;
    const int g1 = (lane >> 3) & 1;
    const int g2 = lane >> 4;
    const int r8 = lane & 7;
    const int K = DM;
    const int KT = K >> 7;

    float acc[MT][8][4];
#pragma unroll
    for (int mt = 0; mt < MT; mt++)
#pragma unroll
        for (int nt = 0; nt < 8; nt++)
#pragma unroll
            for (int i = 0; i < 4; i++) acc[mt][nt][i] = 0.f;

    auto load_stage = [&](int stg, int kt) {
        uint32_t sa = smem_u32(sm + stg * STAGE);
        uint32_t sb = sa + A_WORDS * 4;
#pragma unroll
        for (int i = 0; i < MT * 4; i++) {
            int chunk = tid + i * 256;
            int m = chunk >> 4;
            int c = chunk & 15;
            int cs = c ^ (m & 7);
            cp_async16(sa + (uint32_t)(m * 256 + cs * 16),
                       Abase + (size_t)m * K + kt * 128 + c * 8);
        }
#pragma unroll
        for (int i = 0; i < 8; i++) {
            int chunk = tid + i * 256;
            int k = chunk >> 4;
            int c = chunk & 15;
            int cs = c ^ (k & 7);
            cp_async16(sb + (uint32_t)(k * 256 + cs * 16),
                       Bbase + (size_t)(kt * 128 + k) * N + c * 8);
        }
    };

    load_stage(0, 0); CP_COMMIT();
    load_stage(1, 1); CP_COMMIT();

    for (int kt = 0; kt < KT; kt++) {
        if (kt + 1 < KT) { CP_WAIT1(); } else { CP_WAIT0(); }
        __syncthreads();

        uint32_t sa = smem_u32(sm + (kt & 1) * STAGE);
        uint32_t sb = sa + A_WORDS * 4;

#pragma unroll
        for (int s = 0; s < 8; s++) {
            uint32_t bfr[8][2];
#pragma unroll
            for (int nt16 = 0; nt16 < 4; nt16++) {
                int kl = 16 * s + 8 * g1 + r8;
                int ch = (warp_n * 8 + 2 * nt16 + g2) ^ r8;
                uint32_t b4[4];
                ldsm_x4_trans(b4, sb + (uint32_t)(kl * 256 + ch * 16));
                bfr[2 * nt16][0] = b4[0];
                bfr[2 * nt16][1] = b4[1];
                bfr[2 * nt16 + 1][0] = b4[2];
                bfr[2 * nt16 + 1][1] = b4[3];
            }
#pragma unroll
            for (int mt = 0; mt < MT; mt++) {
                int ml = warp_m * (MT * 16) + mt * 16 + 8 * g1 + r8;
                int ch = (2 * s + g2) ^ r8;
                uint32_t af[4];
                ldsm_x4(af, sa + (uint32_t)(ml * 256 + ch * 16));
#pragma unroll
                for (int nt = 0; nt < 8; nt++)
                    mma_f16(acc[mt][nt], af, bfr[nt]);
            }
        }
        __syncthreads();
        if (kt + 2 < KT) { load_stage(kt & 1, kt + 2); CP_COMMIT(); }
    }

#pragma unroll
    for (int mt = 0; mt < MT; mt++) {
        int r = warp_m * (MT * 16) + mt * 16 + grp;
#pragma unroll
        for (int nt = 0; nt < 8; nt++) {
            int c = warp_n * 64 + nt * 8 + 2 * tg;
            size_t o0 = (size_t)r * N + c;
            size_t o1 = (size_t)(r + 8) * N + c;
            *(__half2*)(OutBase + o0) = __floats2half2_rn(acc[mt][nt][0], acc[mt][nt][1]);
            *(__half2*)(OutBase + o1) = __floats2half2_rn(acc[mt][nt][2], acc[mt][nt][3]);
        }
    }
}

// ---------------------------------------------------------------------------
// Merged QKV projection, mixed granularity: 512 CTAs.
// b in [0,128):   Q, BM=256 (16 cols x 8 rows)       -- fills wave 1
// b in [128,320): K, BM=128 (8 cols x 24 rows)       -- backfill
// b in [320,512): V, BM=128 (8 cols x 24 rows)       -- backfill
// ---------------------------------------------------------------------------
__global__ void __launch_bounds__(256, 1) qkv_gemm_kernel(
    const __half* __restrict__ hnorm, const __half* __restrict__ hknorm,
    const __half* __restrict__ wq, const __half* __restrict__ wk,
    const __half* __restrict__ wv,
    __half* __restrict__ qh, __half* __restrict__ kh, __half* __restrict__ vh) {
    extern __shared__ float sm[];
    int b = blockIdx.x;
    if (b < 128) {
        int col0 = (b & 15) * 128;
        int row0 = (b >> 4) * 256;
        qkv_tile<4>(hnorm + (size_t)row0 * DM, wq + col0,
                    qh + (size_t)row0 * 2048 + col0, 2048, sm);
    } else if (b < 320) {
        int t = b - 128;
        int col0 = (t & 7) * 128;
        int row0 = (t >> 3) * 128;
        qkv_tile<2>(hknorm + (size_t)row0 * DM, wk + col0,
                    kh + (size_t)row0 * 1024 + col0, 1024, sm);
    } else {
        int t = b - 320;
        int col0 = (t & 7) * 128;
        int row0 = (t >> 3) * 128;
        qkv_tile<2>(hknorm + (size_t)row0 * DM, wv + col0,
                    vh + (size_t)row0 * 1024 + col0, 1024, sm);
    }
}

// ---------------------------------------------------------------------------
// Fused gate+up+SiLU dual GEMM v2 (validated round 16): BM=256, BN=64, BK=128.
// ---------------------------------------------------------------------------
#define M3_A_WORDS (256 * 64)
#define M3_B_WORDS (128 * 32)
#define M3_STAGE   (M3_A_WORDS + 2 * M3_B_WORDS)
#define M3_SMEM_BYTES (2 * M3_STAGE * 4)

__global__ void __launch_bounds__(256, 1) dual_gemm_silu_kernel(
    const __half* __restrict__ A, const __half* __restrict__ Bg,
    const __half* __restrict__ Bu, __half* __restrict__ Out,
    int M, int N, int K) {
    extern __shared__ float sm[];
    const int tid = threadIdx.x;
    const int lane = tid & 31;
    const int wid = tid >> 5;
    const int warp_m = wid & 3;
    const int warp_n = wid >> 2;
    const int grp = lane >> 2;
    const int tg = lane & 3;
    const int g1 = (lane >> 3) & 1;
    const int g2 = lane >> 4;
    const int r8 = lane & 7;

    const int row0 = blockIdx.y * 256;
    const int col0 = blockIdx.x * 64;
    const __half* Abase = A + (size_t)row0 * K;
    const __half* Bgb = Bg + col0;
    const __half* Bub = Bu + col0;
    const int KT = K >> 7;

    float acc_g[4][4][4], acc_u[4][4][4];
#pragma unroll
    for (int mt = 0; mt < 4; mt++)
#pragma unroll
        for (int nt = 0; nt < 4; nt++)
#pragma unroll
            for (int i = 0; i < 4; i++) { acc_g[mt][nt][i] = 0.f; acc_u[mt][nt][i] = 0.f; }

    auto load_stage = [&](int stg, int kt) {
        uint32_t sa = smem_u32(sm + stg * M3_STAGE);
        uint32_t sg = sa + M3_A_WORDS * 4;
        uint32_t su = sg + M3_B_WORDS * 4;
#pragma unroll
        for (int i = 0; i < 16; i++) {
            int chunk = tid + i * 256;
            int m = chunk >> 4;
            int c = chunk & 15;
            int cs = c ^ (m & 7);
            cp_async16(sa + (uint32_t)(m * 256 + cs * 16),
                       Abase + (size_t)m * K + kt * 128 + c * 8);
        }
#pragma unroll
        for (int i = 0; i < 4; i++) {
            int chunk = tid + i * 256;
            int k = chunk >> 3;
            int c = chunk & 7;
            int cs = c ^ (k & 7);
            cp_async16(sg + (uint32_t)(k * 128 + cs * 16),
                       Bgb + (size_t)(kt * 128 + k) * N + c * 8);
        }
#pragma unroll
        for (int i = 0; i < 4; i++) {
            int chunk = tid + i * 256;
            int k = chunk >> 3;
            int c = chunk & 7;
            int cs = c ^ (k & 7);
            cp_async16(su + (uint32_t)(k * 128 + cs * 16),
                       Bub + (size_t)(kt * 128 + k) * N + c * 8);
        }
    };

    load_stage(0, 0); CP_COMMIT();
    if (KT > 1) load_stage(1, 1);
    CP_COMMIT();

    for (int kt = 0; kt < KT; kt++) {
        if (kt + 1 < KT) { CP_WAIT1(); } else { CP_WAIT0(); }
        __syncthreads();

        uint32_t sa = smem_u32(sm + (kt & 1) * M3_STAGE);
        uint32_t sg = sa + M3_A_WORDS * 4;
        uint32_t su = sg + M3_B_WORDS * 4;

#pragma unroll
        for (int s = 0; s < 8; s++) {
            uint32_t af[4][4];
#pragma unroll
            for (int mt = 0; mt < 4; mt++) {
                int ml = warp_m * 64 + mt * 16 + 8 * g1 + r8;
                int ch = (2 * s + g2) ^ r8;
                ldsm_x4(af[mt], sa + (uint32_t)(ml * 256 + ch * 16));
            }
            uint32_t bg[4][2], bu[4][2];
#pragma unroll
            for (int nt16 = 0; nt16 < 2; nt16++) {
                int kl = 16 * s + 8 * g1 + r8;
                int ch = (warp_n * 4 + 2 * nt16 + g2) ^ r8;
                uint32_t b4[4];
                ldsm_x4_trans(b4, sg + (uint32_t)(kl * 128 + ch * 16));
                bg[2 * nt16][0] = b4[0]; bg[2 * nt16][1] = b4[1];
                bg[2 * nt16 + 1][0] = b4[2]; bg[2 * nt16 + 1][1] = b4[3];
                ldsm_x4_trans(b4, su + (uint32_t)(kl * 128 + ch * 16));
                bu[2 * nt16][0] = b4[0]; bu[2 * nt16][1] = b4[1];
                bu[2 * nt16 + 1][0] = b4[2]; bu[2 * nt16 + 1][1] = b4[3];
            }
#pragma unroll
            for (int mt = 0; mt < 4; mt++)
#pragma unroll
                for (int nt = 0; nt < 4; nt++) {
                    mma_f16(acc_g[mt][nt], af[mt], bg[nt]);
                    mma_f16(acc_u[mt][nt], af[mt], bu[nt]);
                }
        }
        __syncthreads();
        if (kt + 2 < KT) { load_stage(kt & 1, kt + 2); CP_COMMIT(); }
    }

#pragma unroll
    for (int mt = 0; mt < 4; mt++) {
        int r = row0 + warp_m * 64 + mt * 16 + grp;
#pragma unroll
        for (int nt = 0; nt < 4; nt++) {
            int c = col0 + warp_n * 32 + nt * 8 + 2 * tg;
            float gx = acc_g[mt][nt][0], gy = acc_g[mt][nt][1];
            float gz = acc_g[mt][nt][2], gw = acc_g[mt][nt][3];
            *(__half2*)(Out + (size_t)r * N + c) = __floats2half2_rn(
                gx / (1.f + expf(-gx)) * acc_u[mt][nt][0],
                gy / (1.f + expf(-gy)) * acc_u[mt][nt][1]);
            *(__half2*)(Out + (size_t)(r + 8) * N + c) = __floats2half2_rn(
                gz / (1.f + expf(-gz)) * acc_u[mt][nt][2],
                gw / (1.f + expf(-gw)) * acc_u[mt][nt][3]);
        }
    }
}

// ---------------------------------------------------------------------------
// FP16 flash attention, GQA-paired, BQ=128, materialized mask (gm).
// Grid (SQ/128, NKV) = 128 CTAs. (Round-13 validated version.)
// ---------------------------------------------------------------------------
#define FL_TILES (SKK / 64)
#define FLH_QS   0
#define FLH_KS   16384
#define FLH_VT   24576
#define FLH_PS   32768
#define FLH_PH   40960
#define FLH_MI   45056
#define FLH_LI   45312
#define FLH_CORR 45568
#define FL_BYTES ((45568 + 256) * 4)

__global__ void __launch_bounds__(256, 1) flash_tc_kernel(
    const __half* __restrict__ Q, const __half* __restrict__ Kg,
    const __half* __restrict__ Vg, const float* __restrict__ gm,
    __half* __restrict__ ctx) {
    extern __shared__ float sm[];
    float* Qs = sm + FLH_QS;
    float* Ks = sm + FLH_KS;
    float* Vt = sm + FLH_VT;
    float* Ps = sm + FLH_PS;
    float* Ph = sm + FLH_PH;
    float* mi = sm + FLH_MI;
    float* li = sm + FLH_LI;
    float* corr = sm + FLH_CORR;

    const int tid = threadIdx.x;
    const int lane = tid & 31;
    const int wrp = tid >> 5;
    const int warp_m = wrp & 3;
    const int warp_n = wrp >> 2;
    const int grp = lane >> 2;
    const int tg = lane & 3;
    const int q0 = blockIdx.x << 7;
    const int hk = blockIdx.y;
    const int h0 = hk << 1;

    const float scale = 0.08838834764831845f;
    const float LOG2E = 1.44269504088896340736f;

#pragma unroll
    for (int i = 0; i < 16; i++) {
        int chunk = tid + i * 256;
        int hh = chunk >> 11;
        int rc = chunk & 2047;
        int row = rc >> 4;
        int jc = rc & 15;
        int c = jc >> 3, j = jc & 7;
        int pj = (j + 2 * (row & 3)) & 7;
        cp_async16(smem_u32(Qs + hh * 8192 + (c * 128 + row) * 32 + pj * 4),
                   Q + (size_t)(q0 + row) * (NH * HD) + (h0 + hh) * HD + jc * 8);
    }
#pragma unroll
    for (int i = 0; i < 4; i++) {
        int chunk = tid + i * 256;
        int row = chunk >> 4;
        int jc = chunk & 15;
        int c = jc >> 3, j = jc & 7;
        int pj = (j + 2 * (row & 3)) & 7;
        cp_async16(smem_u32(Ks + (c * 64 + row) * 32 + pj * 4),
                   Kg + (size_t)row * (NKV * HD) + hk * HD + jc * 8);
    }
    CP_COMMIT();

    mi[tid] = -INFINITY;
    li[tid] = 0.f;

    float acc_o[2][2][8][4];
#pragma unroll
    for (int hh = 0; hh < 2; hh++)
#pragma unroll
        for (int mt = 0; mt < 2; mt++)
#pragma unroll
            for (int nt = 0; nt < 8; nt++)
#pragma unroll
                for (int i = 0; i < 4; i++) acc_o[hh][mt][nt][i] = 0.f;

    const int jp = tid & 31;
    const int dbase = (tid >> 5) * 16;
    uint4 vra[2], vrb[2];
    {
        const __half* pa = Vg + (size_t)(2 * jp) * (NKV * HD) + hk * HD + dbase;
        const __half* pb = Vg + (size_t)(2 * jp + 1) * (NKV * HD) + hk * HD + dbase;
        vra[0] = *(const uint4*)pa; vra[1] = *(const uint4*)(pa + 8);
        vrb[0] = *(const uint4*)pb; vrb[1] = *(const uint4*)(pb + 8);
    }

    for (int kt = 0; kt < FL_TILES; kt++) {
        const int buf = kt & 1;
        const int k0 = kt << 6;
        const float* KsB = Ks + buf * 4096;
        const float* VtB = Vt + buf * 4096;

        __syncthreads();   // (a)

        {
            float* VtW = Vt + buf * 4096;
            const __half* ha = (const __half*)vra;
            const __half* hb = (const __half*)vrb;
            int j = jp >> 2, kin = jp & 3;
#pragma unroll
            for (int d = 0; d < 16; d++) {
                int row = dbase + d;
                int pj = (j + 2 * (row & 3)) & 7;
                *(__half2*)(VtW + row * 32 + pj * 4 + kin) =
                    __halves2half2(ha[d], hb[d]);
            }
        }
        if (kt + 1 < FL_TILES) {
            int k0n = k0 + 64;
#pragma unroll
            for (int i = 0; i < 4; i++) {
                int chunk = tid + i * 256;
                int row = chunk >> 4;
                int jc = chunk & 15;
                int c = jc >> 3, j = jc & 7;
                int pj = (j + 2 * (row & 3)) & 7;
                cp_async16(smem_u32(Ks + (buf ^ 1) * 4096 + (c * 64 + row) * 32 + pj * 4),
                           Kg + (size_t)(k0n + row) * (NKV * HD) + hk * HD + jc * 8);
            }
            CP_COMMIT();
            const __half* pa = Vg + (size_t)(k0n + 2 * jp) * (NKV * HD) + hk * HD + dbase;
            const __half* pb = Vg + (size_t)(k0n + 2 * jp + 1) * (NKV * HD) + hk * HD + dbase;
            vra[0] = *(const uint4*)pa; vra[1] = *(const uint4*)(pa + 8);
            vrb[0] = *(const uint4*)pb; vrb[1] = *(const uint4*)(pb + 8);
            CP_WAIT1();
        } else {
            CP_WAIT0();
        }
        __syncthreads();   // (b)

#pragma unroll
        for (int hh = 0; hh < 2; hh++) {
            const float* QsH = Qs + hh * 8192;

            float accs[2][4][4];
#pragma unroll
            for (int mt = 0; mt < 2; mt++)
#pragma unroll
                for (int nt = 0; nt < 4; nt++)
#pragma unroll
                    for (int i = 0; i < 4; i++) accs[mt][nt][i] = 0.f;
#pragma unroll
            for (int c = 0; c < 2; c++)
#pragma unroll
                for (int s = 0; s < 4; s++) {
                    int off = 2 * ((4 * s + tg + 4 * (grp & 3)) & 15);
                    uint32_t bf[4][2];
#pragma unroll
                    for (int nt = 0; nt < 4; nt++) {
                        int rb = warp_n * 32 + nt * 8 + grp;
                        float2 bv = *(const float2*)(KsB + (c * 64 + rb) * 32 + off);
                        bf[nt][0] = __float_as_uint(bv.x);
                        bf[nt][1] = __float_as_uint(bv.y);
                    }
#pragma unroll
                    for (int mt = 0; mt < 2; mt++) {
                        int rm = warp_m * 32 + mt * 16 + grp;
                        const float* ab = QsH + (c * 128 + rm) * 32 + off;
                        float2 pa = *(const float2*)ab;
                        float2 qa = *(const float2*)(ab + 8 * 32);
                        uint32_t af[4] = {__float_as_uint(pa.x), __float_as_uint(qa.x),
                                          __float_as_uint(pa.y), __float_as_uint(qa.y)};
#pragma unroll
                        for (int nt = 0; nt < 4; nt++)
                            mma_f16(accs[mt][nt], af, bf[nt]);
                    }
                }

#pragma unroll
            for (int mt = 0; mt < 2; mt++) {
                int r0 = warp_m * 32 + mt * 16 + grp, r1 = r0 + 8;
                const float* g0 = gm + (size_t)(q0 + r0) * SKK + k0;
                const float* g1 = gm + (size_t)(q0 + r1) * SKK + k0;
#pragma unroll
                for (int nt = 0; nt < 4; nt++) {
                    int cn = warp_n * 32 + nt * 8 + 2 * tg;
                    float2 m0 = *(const float2*)(g0 + cn);
                    float2 m1 = *(const float2*)(g1 + cn);
                    int c = cn >> 5, k32 = cn & 31;
                    int pj = ((k32 >> 2) + 2 * (r0 & 3)) & 7;
                    int kin = k32 & 3;
                    float2 o0 = make_float2(accs[mt][nt][0] * scale + m0.x,
                                            accs[mt][nt][1] * scale + m0.y);
                    float2 o1 = make_float2(accs[mt][nt][2] * scale + m1.x,
                                            accs[mt][nt][3] * scale + m1.y);
                    *(float2*)(Ps + (c * 128 + r0) * 32 + pj * 4 + kin) = o0;
                    *(float2*)(Ps + (c * 128 + r1) * 32 + pj * 4 + kin) = o1;
                }
            }
            __syncthreads();   // (c)

            {
                int row = tid >> 1, c = tid & 1;
                const float* base = Ps + (c * 128 + row) * 32;
                float4 v[8];
#pragma unroll
                for (int jj = 0; jj < 8; jj++) {
                    int pjs = (jj + 2 * (row & 3)) & 7;
                    v[jj] = *(const float4*)(base + pjs * 4);
                }
                float m_old = mi[hh * 128 + row];
                float m = m_old;
#pragma unroll
                for (int jj = 0; jj < 8; jj++)
                    m = fmaxf(m, fmaxf(fmaxf(v[jj].x, v[jj].y), fmaxf(v[jj].z, v[jj].w)));
                m = fmaxf(m, __shfl_xor_sync(0xffffffffu, m, 1));
                float l = 0.f;
#pragma unroll
                for (int jj = 0; jj < 8; jj++) {
                    float px = exp2f((v[jj].x - m) * LOG2E);
                    float py = exp2f((v[jj].y - m) * LOG2E);
                    float pz = exp2f((v[jj].z - m) * LOG2E);
                    float pw = exp2f((v[jj].w - m) * LOG2E);
                    l += (px + py) + (pz + pw);
                    int ck0 = c * 16 + jj * 2;
#pragma unroll
                    for (int p = 0; p < 2; p++) {
                        int ck = ck0 + p;
                        int jh = ck >> 2, kinh = ck & 3;
                        int pjh = (jh + 2 * (row & 3)) & 7;
                        __half2 hv = (p == 0) ? __floats2half2_rn(px, py)
                                              : __floats2half2_rn(pz, pw);
                        *(__half2*)(Ph + row * 32 + pjh * 4 + kinh) = hv;
                    }
                }
                l += __shfl_xor_sync(0xffffffffu, l, 1);
                if (c == 0) {
                    float cr = exp2f((m_old - m) * LOG2E);
                    corr[hh * 128 + row] = cr;
                    li[hh * 128 + row] = li[hh * 128 + row] * cr + l;
                    mi[hh * 128 + row] = m;
                }
            }
            __syncthreads();   // (d)

            {
#pragma unroll
                for (int mt = 0; mt < 2; mt++) {
                    int rm = warp_m * 32 + mt * 16 + grp;
                    float cr0 = corr[hh * 128 + rm];
                    float cr1 = corr[hh * 128 + rm + 8];
#pragma unroll
                    for (int nt = 0; nt < 8; nt++) {
                        acc_o[hh][mt][nt][0] *= cr0; acc_o[hh][mt][nt][1] *= cr0;
                        acc_o[hh][mt][nt][2] *= cr1; acc_o[hh][mt][nt][3] *= cr1;
                    }
                }
#pragma unroll
                for (int s = 0; s < 4; s++) {
                    int off = 2 * ((4 * s + tg + 4 * (grp & 3)) & 15);
                    uint32_t bf[8][2];
#pragma unroll
                    for (int nt = 0; nt < 8; nt++) {
                        int rb = warp_n * 64 + nt * 8 + grp;
                        float2 bv = *(const float2*)(VtB + rb * 32 + off);
                        bf[nt][0] = __float_as_uint(bv.x);
                        bf[nt][1] = __float_as_uint(bv.y);
                    }
#pragma unroll
                    for (int mt = 0; mt < 2; mt++) {
                        int rm = warp_m * 32 + mt * 16 + grp;
                        float2 pa = *(const float2*)(Ph + rm * 32 + off);
                        float2 qa = *(const float2*)(Ph + (rm + 8) * 32 + off);
                        uint32_t af[4] = {__float_as_uint(pa.x), __float_as_uint(qa.x),
                                          __float_as_uint(pa.y), __float_as_uint(qa.y)};
#pragma unroll
                        for (int nt = 0; nt < 8; nt++)
                            mma_f16(acc_o[hh][mt][nt], af, bf[nt]);
                    }
                }
            }
        }
    }

#pragma unroll
    for (int hh = 0; hh < 2; hh++)
#pragma unroll
        for (int mt = 0; mt < 2; mt++) {
            int lr0 = warp_m * 32 + mt * 16 + grp;
            float inv0 = 1.f / li[hh * 128 + lr0];
            float inv1 = 1.f / li[hh * 128 + lr0 + 8];
            __half* p0 = ctx + (size_t)(q0 + lr0) * (NH * HD) + (h0 + hh) * HD;
            __half* p1 = ctx + (size_t)(q0 + lr0 + 8) * (NH * HD) + (h0 + hh) * HD;
#pragma unroll
            for (int nt = 0; nt < 8; nt++) {
                int col = warp_n * 64 + nt * 8 + 2 * tg;
                *(__half2*)(p0 + col) = __floats2half2_rn(acc_o[hh][mt][nt][0] * inv0,
                                                          acc_o[hh][mt][nt][1] * inv0);
                *(__half2*)(p1 + col) = __floats2half2_rn(acc_o[hh][mt][nt][2] * inv1,
                                                          acc_o[hh][mt][nt][3] * inv1);
            }
        }
}

// ---------------------------------------------------------------------------
// Launch sequence. Profiled launch = #4: merged QKV GEMM.
// ---------------------------------------------------------------------------
extern "C" void kernel_launch(void* const* d_in, const int* in_sizes, int n_in,
                              void* d_out, int out_size) {
    const float* hidden_states = (const float*)d_in[0];
    const float* kv_hidden     = (const float*)d_in[1];
    const float* causal_mask   = (const float*)d_in[2];
    const float* w_q    = (const float*)d_in[3];
    const float* w_k    = (const float*)d_in[4];
    const float* w_v    = (const float*)d_in[5];
    const float* w_o    = (const float*)d_in[6];
    const float* q_nw   = (const float*)d_in[7];
    const float* k_nw   = (const float*)d_in[8];
    const float* ln1    = (const float*)d_in[9];
    const float* ln2    = (const float*)d_in[10];
    const float* w_gate = (const float*)d_in[11];
    const float* w_up   = (const float*)d_in[12];
    const float* w_down = (const float*)d_in[13];
    const int* positions    = (const int*)d_in[14];
    const int* kv_positions = (const int*)d_in[15];
    const int* hs_idxs      = (const int*)d_in[16];
    const int* key_idxs     = (const int*)d_in[17];
    float* out = (float*)d_out;

    __half *hnorm, *hknorm, *qh, *kh, *vh, *ctx, *h2, *act;
    float *hid, *ct, *st, *gm;
    double* dinv;
    __half *wqh, *wkh, *wvh, *woh, *wgh, *wuh, *wdh;
    cudaGetSymbolAddress((void**)&hnorm,  g_hnorm);
    cudaGetSymbolAddress((void**)&hknorm, g_hknorm);
    cudaGetSymbolAddress((void**)&qh,     g_qh);
    cudaGetSymbolAddress((void**)&kh,     g_kh);
    cudaGetSymbolAddress((void**)&vh,     g_vh);
    cudaGetSymbolAddress((void**)&ctx,    g_ctx);
    cudaGetSymbolAddress((void**)&hid,    g_hidden);
    cudaGetSymbolAddress((void**)&h2,     g_h2);
    cudaGetSymbolAddress((void**)&act,    g_act);
    cudaGetSymbolAddress((void**)&ct,     g_cos);
    cudaGetSymbolAddress((void**)&st,     g_sin);
    cudaGetSymbolAddress((void**)&dinv,   g_inv);
    cudaGetSymbolAddress((void**)&gm,     g_mask);
    cudaGetSymbolAddress((void**)&wqh,    g_wqh);
    cudaGetSymbolAddress((void**)&wkh,    g_wkh);
    cudaGetSymbolAddress((void**)&wvh,    g_wvh);
    cudaGetSymbolAddress((void**)&woh,    g_woh);
    cudaGetSymbolAddress((void**)&wgh,    g_wgh);
    cudaGetSymbolAddress((void**)&wuh,    g_wuh);
    cudaGetSymbolAddress((void**)&wdh,    g_wdh);

    cudaFuncSetAttribute(flash_tc_kernel, cudaFuncAttributeMaxDynamicSharedMemorySize,
                         FL_BYTES);
    cudaFuncSetAttribute(mma_gemm_kernel, cudaFuncAttributeMaxDynamicSharedMemorySize,
                         G2_SMEM_BYTES);
    cudaFuncSetAttribute(qkv_gemm_kernel, cudaFuncAttributeMaxDynamicSharedMemorySize,
                         G2_SMEM_BYTES);
    cudaFuncSetAttribute(dual_gemm_silu_kernel, cudaFuncAttributeMaxDynamicSharedMemorySize,
                         M3_SMEM_BYTES);

    CvtArgs ca;
    ca.src[0] = w_q;    ca.dst[0] = wqh;
    ca.src[1] = w_k;    ca.dst[1] = wkh;
    ca.src[2] = w_v;    ca.dst[2] = wvh;
    ca.src[3] = w_o;    ca.dst[3] = woh;
    ca.src[4] = w_gate; ca.dst[4] = wgh;
    ca.src[5] = w_up;   ca.dst[5] = wuh;
    ca.src[6] = w_down; ca.dst[6] = wdh;
    ca.end[0] = 4096;
    ca.end[1] = 4096 + 2048;
    ca.end[2] = 4096 + 2048 + 2048;
    ca.end[3] = 4096 + 2048 + 2048 + 4096;
    ca.end[4] = 4096 + 2048 + 2048 + 4096 + 12288;
    ca.end[5] = 4096 + 2048 + 2048 + 4096 + 12288 + 12288;
    ca.end[6] = 4096 + 2048 + 2048 + 4096 + 12288 + 12288 + 12288;

    // #1..#3
    convert_all_kernel<<<ca.end[6], 256>>>(ca);
    rmsnorm2_kernel<<<SQ + SKK, 256>>>(hidden_states, hnorm, kv_hidden, hknorm, ln1, DM);
    rope_inv_kernel<<<1, 64>>>(dinv);
    // #4 <- profiled: merged QKV projection, mixed granularity (512 CTAs)
    qkv_gemm_kernel<<<512, 256, G2_SMEM_BYTES>>>(
        hnorm, hknorm, wqh, wkh, wvh, qh, kh, vh);

    rope_table_kernel<<<TT, 64>>>(dinv, ct, st);
    gather_mask_kernel<<<dim3(SKK / 256, SQ), 256>>>(causal_mask, hs_idxs, key_idxs, gm);

    qknorm_rope_kernel<<<SQ * NH / 4, 512>>>(qh, q_nw, positions, ct, st, NH);
    qknorm_rope_kernel<<<SKK * NKV / 4, 512>>>(kh, k_nw, kv_positions, ct, st, NKV);

    // BQ=128 GQA-paired flash (materialized gm)
    flash_tc_kernel<<<dim3(SQ / 128, NKV), 256, FL_BYTES>>>(qh, kh, vh, gm, ctx);

    mma_gemm_kernel<<<dim3(DM / 128, SQ / 256), 256, G2_SMEM_BYTES>>>(
        ctx, woh, hidden_states, hid, nullptr, SQ, DM, 2048, 1);

    rmsnorm_kernel<<<SQ, 256>>>(hid, ln2, h2, DM);

    dual_gemm_silu_kernel<<<dim3(FF / 64, SQ / 256), 256, M3_SMEM_BYTES>>>(
        h2, wgh, wuh, act, SQ, FF, DM);
    mma_gemm_kernel<<<dim3(DM / 128, SQ / 256), 256, G2_SMEM_BYTES>>>(
        act, wdh, hid, out, nullptr, SQ, DM, FF, 1);
}